// round 11
// baseline (speedup 1.0000x reference)
#include <cuda_runtime.h>
#include <cuda_bf16.h>
#include <math.h>
#include <stdint.h>
#include <string.h>

// Problem constants
#define BATCH 32
#define CIN   8
#define COUT  8
#define KP    4
#define DIN   16
#define DOUT  16
#define SS_   32
#define EPSV  1e-5f

#define NPTS  (BATCH*SS_*SS_)      // 32768 spatial points (b,y,x)
#define NOC   (CIN*COUT*DOUT)      // 1024 conv output channels
#define KDIM  144                  // GEMM K (fp32)
#define KE2   288                  // [hi(144) | lo(144)] bf16 layout
#define OD    (COUT*DOUT)          // 128 (o,d) pairs per point

typedef unsigned long long u64;

__device__ __forceinline__ uint32_t smem_u32(const void* p) {
    uint32_t a;
    asm("{ .reg .u64 t; cvta.to.shared.u64 t, %1; cvt.u32.u64 %0, t; }" : "=r"(a) : "l"(p));
    return a;
}
#define CP_ASYNC16(dst, src) asm volatile("cp.async.cg.shared.global [%0], [%1], 16;" :: "r"(dst), "l"(src))
#define CP_COMMIT()          asm volatile("cp.async.commit_group;" ::: "memory")

#define MMA16816(d, a0, a1, a2, a3, b0, b1) \
    asm volatile("mma.sync.aligned.m16n8k16.row.col.f32.bf16.bf16.f32 " \
        "{%0,%1,%2,%3},{%4,%5,%6,%7},{%8,%9},{%0,%1,%2,%3};" \
        : "+f"((d)[0]), "+f"((d)[1]), "+f"((d)[2]), "+f"((d)[3]) \
        : "r"(a0), "r"(a1), "r"(a2), "r"(a3), "r"(b0), "r"(b1))

// ---------------- scratch (device globals) --------------------------------
__device__ __align__(128) __nv_bfloat16 g_Ab[NPTS*KE2];    // im2col A [p][hi144|lo144]
__device__ __align__(128) __nv_bfloat16 g_Bb[NOC*KE2];     // permuted weights [n'][hi|lo]
__device__ __align__(128) float g_sumAtt[NPTS*OD];
__device__ __align__(128) float g_pmax[NPTS*OD];
__device__ __align__(128) float g_pmean[NPTS*OD];
__device__ __align__(128) float g_gate[NPTS*OD];
__device__ float g_psumArr[1024*8];
__device__ float g_pssArr[1024*8];
__device__ float g_bnMu[8];
__device__ float g_bnRstd[8];

// ---------------- kernel: prep B (split + N-permute) ----------------------
// n' = o*128 + d*8 + ci  <-  original oc = ci*128 + o*16 + d
__global__ void k_prepB(const float* __restrict__ Wt) {
    int idx = blockIdx.x * 256 + threadIdx.x;   // 1152 blocks exact (294912)
    int n = idx / KE2, e = idx % KE2;
    int o = n >> 7, d = (n >> 3) & 15, ci = n & 7;
    int oc = ci*128 + o*16 + d;
    int t = e / KDIM, k = e - t*KDIM;
    float w = Wt[oc*KDIM + k];
    float hi = __bfloat162float(__float2bfloat16_rn(w));
    float v = t ? (w - hi) : hi;
    g_Bb[idx] = __float2bfloat16_rn(v);
}

// ---------------- kernel: prep A (im2col + split -> bf16 [p][288]) --------
__global__ __launch_bounds__(256) void k_prepA(const float* __restrict__ caps) {
    extern __shared__ char dyn_sm[];
    float* raw = (float*)dyn_sm;                   // 2048 f
    uint32_t* outp = (uint32_t*)(dyn_sm + 8192);   // [64][145] u32
    int tid = threadIdx.x;
    int m064 = blockIdx.x * 64;
    int b = m064 >> 10;
    int y0 = (m064 & 1023) >> 5;
    for (int i = tid; i < 2048; i += 256) {
        int din = i >> 7, rem = i & 127, yy = y0 - 1 + (rem >> 5), x = rem & 31;
        raw[i] = ((unsigned)yy < 32u) ? caps[b*16384 + din*1024 + yy*32 + x] : 0.f;
    }
    __syncthreads();
    int p = tid & 63, part = tid >> 6;
    int y_local = p >> 5, x = p & 31;
    bool isLo = part >= 2;
    int j0 = (part & 1) * 36;
    for (int j = j0; j < j0 + 36; j++) {
        float v[2];
#pragma unroll
        for (int q = 0; q < 2; q++) {
            int k = 2*j + q;
            int din = k / 9, r = k - din*9;
            int ry = r / 3;
            int xx = x + (r - ry*3) - 1;
            v[q] = ((unsigned)xx < 32u) ? raw[din*128 + (y_local + ry)*32 + xx] : 0.f;
        }
        uint32_t u;
        if (!isLo) {
            __nv_bfloat162 h2 = __float22bfloat162_rn(make_float2(v[0], v[1]));
            memcpy(&u, &h2, 4);
            outp[p*145 + j] = u;
        } else {
            float h0 = __bfloat162float(__float2bfloat16_rn(v[0]));
            float h1 = __bfloat162float(__float2bfloat16_rn(v[1]));
            __nv_bfloat162 l2 = __float22bfloat162_rn(make_float2(v[0]-h0, v[1]-h1));
            memcpy(&u, &l2, 4);
            outp[p*145 + 72 + j] = u;
        }
    }
    __syncthreads();
    uint32_t* gdst = (uint32_t*)((char*)g_Ab + (size_t)m064 * (KE2*2));
    for (int i = tid; i < 64*144; i += 256)
        gdst[i] = outp[(i/144)*145 + (i%144)];
}

// ---------------- kernel: fused GEMM + routing ----------------------------
// BM=256, BN=128 (= one o), 512 threads, 3-term bf16 split, 3-stage cp.async.
// Epilogue stages acc through smem (2 x 128-row passes) and computes the
// agreement routing in-block: no votes tensor, no k_route kernel.
#define STG 15360     // elems per stage: A 256x40 + B 128x40
#define OFF_BIAS 92160
#define OFF_WV   92672
#define OFF_BV   (92672 + 256*4)
__device__ __forceinline__ void gload(uint32_t dbase, const char* Asrc,
                                      const char* Bsrc, int c, int tid) {
#pragma unroll
    for (int i = 0; i < 2; i++) {
        int q = i*512 + tid;
        int row = q >> 2, part = q & 3;
        uint32_t dst = dbase + row*80 + ((part < 2) ? 0 : 32) + (part & 1)*16;
        CP_ASYNC16(dst, Asrc + (size_t)row*576 + ((part < 2) ? 0 : 288) + c*32 + (part & 1)*16);
    }
    {
        int row = tid >> 2, part = tid & 3;
        uint32_t dst = dbase + 20480 + row*80 + ((part < 2) ? 0 : 32) + (part & 1)*16;
        CP_ASYNC16(dst, Bsrc + (size_t)row*576 + ((part < 2) ? 0 : 288) + c*32 + (part & 1)*16);
    }
}

__global__ __launch_bounds__(512, 1) void k_gemm(const float* __restrict__ bt,
                                                 const float* __restrict__ Wv,
                                                 const float* __restrict__ bv) {
    extern __shared__ char dyn_sm[];
    __nv_bfloat16* gsm = (__nv_bfloat16*)dyn_sm;
    float* bias_s = (float*)(dyn_sm + OFF_BIAS);
    float* wv_s   = (float*)(dyn_sm + OFF_WV);
    float* bv_s   = (float*)(dyn_sm + OFF_BV);
    const int tid = threadIdx.x;
    const int lane = tid & 31;
    const int wid = tid >> 5;
    const int warpM = wid & 3;     // 4 M-warps (64 rows each)
    const int warpN = wid >> 2;    // 4 N-warps (32 cols each)
    const int o  = blockIdx.x;     // one output channel per block (BN=128)
    const int n0 = o * 128;
    const int m0 = blockIdx.y * 256;
    if (tid < 128) {
        int d = tid >> 3, ci = tid & 7;
        bias_s[tid] = bt[ci*128 + o*16 + d];
    } else if (tid < 384) {
        wv_s[tid - 128] = Wv[o*256 + tid - 128];
    } else if (tid < 416) {
        bv_s[tid - 384] = bv[o*32 + tid - 384];
    }

    const char* Asrc = (const char*)g_Ab + (size_t)m0 * (KE2*2);
    const char* Bsrc = (const char*)g_Bb + (size_t)n0 * (KE2*2);
    const uint32_t sb = smem_u32(gsm);

    gload(sb,           Asrc, Bsrc, 0, tid); CP_COMMIT();
    gload(sb + STG*2,   Asrc, Bsrc, 1, tid); CP_COMMIT();

    float acc[4][4][4];
#pragma unroll
    for (int a = 0; a < 4; a++)
#pragma unroll
        for (int b = 0; b < 4; b++)
#pragma unroll
            for (int c = 0; c < 4; c++) acc[a][b][c] = 0.f;

    const int qr = lane >> 2;
    const int qc = lane & 3;
    const int cb = qc*2;

    for (int c = 0; c < 9; c++) {
        if (c == 8) asm volatile("cp.async.wait_group 0;" ::: "memory");
        else        asm volatile("cp.async.wait_group 1;" ::: "memory");
        __syncthreads();
        if (c + 2 < 9) {
            gload(sb + ((c+2)%3)*STG*2, Asrc, Bsrc, c+2, tid);
            CP_COMMIT();
        }
        const __nv_bfloat16* Sa  = gsm + (c%3)*STG;
        const __nv_bfloat16* Sb2 = Sa + 10240;

        uint32_t ah[4][4], bh[4][2], bl[4][2];
#pragma unroll
        for (int mf = 0; mf < 4; mf++) {
            int r = warpM*64 + mf*16 + qr;
            ah[mf][0] = *(const uint32_t*)&Sa[r*40 + cb];
            ah[mf][1] = *(const uint32_t*)&Sa[(r+8)*40 + cb];
            ah[mf][2] = *(const uint32_t*)&Sa[r*40 + cb + 8];
            ah[mf][3] = *(const uint32_t*)&Sa[(r+8)*40 + cb + 8];
        }
#pragma unroll
        for (int nf = 0; nf < 4; nf++) {
            int n = warpN*32 + nf*8 + qr;
            bh[nf][0] = *(const uint32_t*)&Sb2[n*40 + cb];
            bh[nf][1] = *(const uint32_t*)&Sb2[n*40 + cb + 8];
            bl[nf][0] = *(const uint32_t*)&Sb2[n*40 + cb + 16];
            bl[nf][1] = *(const uint32_t*)&Sb2[n*40 + cb + 24];
        }
#pragma unroll
        for (int mf = 0; mf < 4; mf++)
#pragma unroll
            for (int nf = 0; nf < 4; nf++) {
                MMA16816(acc[mf][nf], ah[mf][0], ah[mf][1], ah[mf][2], ah[mf][3],
                         bh[nf][0], bh[nf][1]);
                MMA16816(acc[mf][nf], ah[mf][0], ah[mf][1], ah[mf][2], ah[mf][3],
                         bl[nf][0], bl[nf][1]);
            }
#pragma unroll
        for (int mf = 0; mf < 4; mf++) {
            int r = warpM*64 + mf*16 + qr;
            uint32_t al0 = *(const uint32_t*)&Sa[r*40 + cb + 16];
            uint32_t al1 = *(const uint32_t*)&Sa[(r+8)*40 + cb + 16];
            uint32_t al2 = *(const uint32_t*)&Sa[r*40 + cb + 24];
            uint32_t al3 = *(const uint32_t*)&Sa[(r+8)*40 + cb + 24];
#pragma unroll
            for (int nf = 0; nf < 4; nf++)
                MMA16816(acc[mf][nf], al0, al1, al2, al3, bh[nf][0], bh[nf][1]);
        }
    }

    // ---- fused routing epilogue (2 passes of 128 rows through smem) ----
    __syncthreads();
    float* tile = (float*)dyn_sm;                 // [128][132] fp32 = 67584 B

#pragma unroll
    for (int pass = 0; pass < 2; pass++) {
        if ((warpM >> 1) == pass) {
            int rb = (warpM & 1) * 64;
#pragma unroll
            for (int mf = 0; mf < 4; mf++) {
                int r0 = rb + mf*16 + qr;
#pragma unroll
                for (int nf = 0; nf < 4; nf++) {
                    int cl = warpN*32 + nf*8 + qc*2;
                    float b0 = bias_s[cl], b1 = bias_s[cl + 1];
                    *(float2*)&tile[r0*132 + cl] =
                        make_float2(acc[mf][nf][0] + b0, acc[mf][nf][1] + b1);
                    *(float2*)&tile[(r0+8)*132 + cl] =
                        make_float2(acc[mf][nf][2] + b0, acc[mf][nf][3] + b1);
                }
            }
        }
        __syncthreads();
        {
            int pl = tid >> 2, dg = tid & 3;
            int pt = m0 + pass*128 + pl;
            float sA4[4], pM4[4], pMe4[4];
#pragma unroll
            for (int j = 0; j < 4; j++) {
                int d = dg*4 + j;
                float4 va = *(const float4*)&tile[pl*132 + d*8];
                float4 vb = *(const float4*)&tile[pl*132 + d*8 + 4];
                float vts[8] = {va.x, va.y, va.z, va.w, vb.x, vb.y, vb.z, vb.w};
                float av = 0.f, ws = 0.f, pmx = -1e30f, ps = 0.f;
#pragma unroll
                for (int c2 = 0; c2 < 8; c2++) {
                    float ks = 0.f, kq = 0.f;
#pragma unroll
                    for (int kp = 0; kp < 4; kp++) {
                        int m = kp*8 + c2;
                        const float* wm = &wv_s[m*8];
                        float v = bv_s[m]
                            + wm[0]*vts[0] + wm[1]*vts[1] + wm[2]*vts[2] + wm[3]*vts[3]
                            + wm[4]*vts[4] + wm[5]*vts[5] + wm[6]*vts[6] + wm[7]*vts[7];
                        ks += v; kq += v*v; ps += v;
                        pmx = fmaxf(pmx, v);
                    }
                    float mu  = ks * 0.25f;
                    float var = fmaxf(kq * 0.25f - mu*mu, 1e-30f);
                    float rs  = rsqrtf(var);
                    av += mu * rs; ws += rs;
                }
                sA4[j]  = av / ws;
                pM4[j]  = pmx;
                pMe4[j] = ps * (1.f/32.f);
            }
            size_t off = (size_t)pt*128 + o*16 + dg*4;
            *(float4*)(g_sumAtt + off) = make_float4(sA4[0], sA4[1], sA4[2], sA4[3]);
            *(float4*)(g_pmax   + off) = make_float4(pM4[0], pM4[1], pM4[2], pM4[3]);
            *(float4*)(g_pmean  + off) = make_float4(pMe4[0], pMe4[1], pMe4[2], pMe4[3]);
        }
        if (pass == 0) __syncthreads();
    }
}

// ---------------- kernel 3: 3D gate conv (3x3x3, pad1) + BN partials -----
// (proven R5/R8 layout: thread = (pt, o), 16 d in registers)
__global__ __launch_bounds__(256) void k_gate(const float* __restrict__ Ws) {
    __shared__ float ws_s[54];
    __shared__ float bsum[8], bss[8];
    int tid = threadIdx.x;
    if (tid < 54) ws_s[tid] = Ws[tid];
    if (tid < 8) { bsum[tid] = 0.f; bss[tid] = 0.f; }
    __syncthreads();

    int pt = blockIdx.x * 32 + (tid >> 3);
    int o  = tid & 7;
    int b  = pt >> 10, yx = pt & 1023;
    int y  = yx >> 5,  x  = yx & 31;

    float acc[16];
#pragma unroll
    for (int d = 0; d < 16; d++) acc[d] = 0.f;

    for (int dy = -1; dy <= 1; dy++) {
        int yy = y + dy;
        if ((unsigned)yy >= 32u) continue;
        for (int dx = -1; dx <= 1; dx++) {
            int xx = x + dx;
            if ((unsigned)xx >= 32u) continue;
            int base = ((b << 10) + (yy << 5) + xx)*128 + (o << 4);
            const float4* pm = (const float4*)(g_pmax  + base);
            const float4* pn = (const float4*)(g_pmean + base);
            float rmx[16], rmn[16];
#pragma unroll
            for (int q = 0; q < 4; q++) {
                float4 a = pm[q]; float4 c = pn[q];
                rmx[q*4+0] = a.x; rmx[q*4+1] = a.y; rmx[q*4+2] = a.z; rmx[q*4+3] = a.w;
                rmn[q*4+0] = c.x; rmn[q*4+1] = c.y; rmn[q*4+2] = c.z; rmn[q*4+3] = c.w;
            }
            int wo = (dy+1)*3 + (dx+1);
#pragma unroll
            for (int kz = 0; kz < 3; kz++) {
                float wm = ws_s[kz*9 + wo];
                float wn = ws_s[27 + kz*9 + wo];
#pragma unroll
                for (int d = 0; d < 16; d++) {
                    int s = d + kz - 1;
                    if (s >= 0 && s < 16) acc[d] += wm*rmx[s] + wn*rmn[s];
                }
            }
        }
    }
    float* gp = g_gate + (size_t)pt*128 + (o << 4);
#pragma unroll
    for (int q = 0; q < 4; q++)
        *(float4*)(gp + q*4) = make_float4(acc[q*4+0], acc[q*4+1], acc[q*4+2], acc[q*4+3]);

    float s1 = 0.f, s2 = 0.f;
#pragma unroll
    for (int d = 0; d < 16; d++) { s1 += acc[d]; s2 += acc[d]*acc[d]; }
    s1 += __shfl_xor_sync(0xffffffffu, s1, 8);
    s2 += __shfl_xor_sync(0xffffffffu, s2, 8);
    s1 += __shfl_xor_sync(0xffffffffu, s1, 16);
    s2 += __shfl_xor_sync(0xffffffffu, s2, 16);
    if ((tid & 31) < 8) { atomicAdd(&bsum[o], s1); atomicAdd(&bss[o], s2); }
    __syncthreads();
    if (tid < 8) {
        g_psumArr[blockIdx.x*8 + tid] = bsum[tid];
        g_pssArr [blockIdx.x*8 + tid] = bss[tid];
    }
}

// ---------------- kernel 3b: BN stats finalize (1024 partials) ------------
__global__ void k_bnstats() {
    __shared__ float ss1[256], ss2[256];
    int tid = threadIdx.x;
    int o = tid & 7, seg = tid >> 3;
    float a = 0.f, c = 0.f;
    for (int i = seg*32; i < seg*32 + 32; i++) {
        a += g_psumArr[i*8 + o];
        c += g_pssArr [i*8 + o];
    }
    ss1[tid] = a; ss2[tid] = c;
    __syncthreads();
    if (tid < 8) {
        float A = 0.f, C = 0.f;
        for (int s = 0; s < 32; s++) { A += ss1[s*8 + tid]; C += ss2[s*8 + tid]; }
        const float inv = 1.f / 524288.f;
        float mu = A * inv;
        float var = C * inv - mu*mu;
        g_bnMu[tid]   = mu;
        g_bnRstd[tid] = rsqrtf(var + EPSV);
    }
}

// ---------------- kernel 4: gate apply + LayerNorm + transpose out -------
#define SM4_STRIDE 1025
__global__ __launch_bounds__(256) void k_final(const float* __restrict__ bn_gamma,
                                               const float* __restrict__ bn_beta,
                                               const float* __restrict__ ln_gamma,
                                               const float* __restrict__ ln_beta,
                                               float* __restrict__ out) {
    extern __shared__ char dyn_sm[];
    float* sm4 = (float*)dyn_sm;
    const int RED = 16*SM4_STRIDE;
    int tid = threadIdx.x;
    int b = blockIdx.x & 31;
    int o = blockIdx.x >> 5;
    float mu = g_bnMu[o], rstd = g_bnRstd[o];
    float gam = bn_gamma[0], bet = bn_beta[0];

    int d   = tid & 15;
    int yxb = tid >> 4;
    const float* gp = g_gate   + (b << 10)*128 + (o << 4) + d;
    const float* sp = g_sumAtt + (b << 10)*128 + (o << 4) + d;
    float s = 0.f, ss = 0.f;
    for (int i = 0; i < 64; i++) {
        int yx = yxb + i*16;
        float gg = gp[yx*128];
        float sa = sp[yx*128];
        float z  = (gg - mu) * rstd * gam + bet;
        float sc = 1.f / (1.f + expf(-z));
        float cn = (1.f + sc) * sa;
        sm4[d*SM4_STRIDE + yx] = cn;
        s += cn; ss += cn*cn;
    }
#pragma unroll
    for (int off = 16; off >= 1; off >>= 1) {
        s  += __shfl_xor_sync(0xffffffffu, s,  off);
        ss += __shfl_xor_sync(0xffffffffu, ss, off);
    }
    int wid = tid >> 5;
    if ((tid & 31) == 0) { sm4[RED + wid] = s; sm4[RED + 8 + wid] = ss; }
    __syncthreads();
    if (tid == 0) {
        float S = 0.f, Q = 0.f;
        for (int w = 0; w < 8; w++) { S += sm4[RED + w]; Q += sm4[RED + 8 + w]; }
        const float inv = 1.f / 16384.f;
        float m = S * inv;
        float var = Q * inv - m*m;
        sm4[RED + 16] = m;
        sm4[RED + 17] = rsqrtf(var + EPSV);
    }
    __syncthreads();
    float m = sm4[RED + 16], r = sm4[RED + 17];
    float* ob = out + ((o*32 + b) << 14);
    for (int i = 0; i < 64; i++) {
        int idx = i*256 + tid;
        float v = sm4[(idx >> 10)*SM4_STRIDE + (idx & 1023)];
        ob[idx] = (v - m) * r * ln_gamma[idx] + ln_beta[idx];
    }
}

// ---------------- launch ------------------------------------------------
extern "C" void kernel_launch(void* const* d_in, const int* in_sizes, int n_in,
                              void* d_out, int out_size) {
    const float* caps = (const float*)d_in[0];
    const float* Wt   = (const float*)d_in[1];
    const float* bt   = (const float*)d_in[2];
    const float* Wv   = (const float*)d_in[3];
    const float* bv   = (const float*)d_in[4];
    const float* Ws   = (const float*)d_in[5];
    const float* bng  = (const float*)d_in[6];
    const float* bnb  = (const float*)d_in[7];
    const float* lng  = (const float*)d_in[8];
    const float* lnb  = (const float*)d_in[9];
    float* out = (float*)d_out;

    const int smemA = 8192 + 64*145*4;            // 45312
    const int smemG = OFF_BV + 32*4;              // 93824
    const int smem4 = (16*SM4_STRIDE + 32) * 4;
    cudaFuncSetAttribute(k_prepA, cudaFuncAttributeMaxDynamicSharedMemorySize, smemA);
    cudaFuncSetAttribute(k_gemm,  cudaFuncAttributeMaxDynamicSharedMemorySize, smemG);
    cudaFuncSetAttribute(k_final, cudaFuncAttributeMaxDynamicSharedMemorySize, smem4);

    k_prepB<<<1152, 256>>>(Wt);
    k_prepA<<<512, 256, smemA>>>(caps);
    k_gemm<<<dim3(8, 128), 512, smemG>>>(bt, Wv, bv);
    k_gate<<<NPTS/32, 256>>>(Ws);
    k_bnstats<<<1, 256>>>();
    k_final<<<256, 256, smem4>>>(bng, bnb, lng, lnb, out);
}

// round 12
// speedup vs baseline: 2.0326x; 2.0326x over previous
#include <cuda_runtime.h>
#include <cuda_bf16.h>
#include <math.h>
#include <stdint.h>
#include <string.h>

// Problem constants
#define BATCH 32
#define CIN   8
#define COUT  8
#define KP    4
#define DIN   16
#define DOUT  16
#define SS_   32
#define EPSV  1e-5f

#define NPTS  (BATCH*SS_*SS_)      // 32768 spatial points (b,y,x)
#define NOC   (CIN*COUT*DOUT)      // 1024 conv output channels
#define KDIM  144                  // GEMM K (fp32)
#define KE2   288                  // [hi(144) | lo(144)] bf16 layout
#define OD    (COUT*DOUT)          // 128 (o,d) pairs per point

typedef unsigned long long u64;

// ---------------- packed f32x2 helpers ------------------------------------
__device__ __forceinline__ u64 pack2(float lo, float hi) {
    u64 d; asm("mov.b64 %0,{%1,%2};" : "=l"(d) : "f"(lo), "f"(hi)); return d;
}
__device__ __forceinline__ u64 ffma2(u64 a, u64 b, u64 c) {
    u64 d; asm("fma.rn.f32x2 %0,%1,%2,%3;" : "=l"(d) : "l"(a), "l"(b), "l"(c)); return d;
}
__device__ __forceinline__ u64 fadd2(u64 a, u64 b) {
    u64 d; asm("add.rn.f32x2 %0,%1,%2;" : "=l"(d) : "l"(a), "l"(b)); return d;
}
__device__ __forceinline__ void unpack2(u64 d, float& lo, float& hi) {
    asm("mov.b64 {%0,%1},%2;" : "=f"(lo), "=f"(hi) : "l"(d));
}

__device__ __forceinline__ uint32_t smem_u32(const void* p) {
    uint32_t a;
    asm("{ .reg .u64 t; cvta.to.shared.u64 t, %1; cvt.u32.u64 %0, t; }" : "=r"(a) : "l"(p));
    return a;
}
#define CP_ASYNC16(dst, src) asm volatile("cp.async.cg.shared.global [%0], [%1], 16;" :: "r"(dst), "l"(src))
#define CP_COMMIT()          asm volatile("cp.async.commit_group;" ::: "memory")

#define MMA16816(d, a0, a1, a2, a3, b0, b1) \
    asm volatile("mma.sync.aligned.m16n8k16.row.col.f32.bf16.bf16.f32 " \
        "{%0,%1,%2,%3},{%4,%5,%6,%7},{%8,%9},{%0,%1,%2,%3};" \
        : "+f"((d)[0]), "+f"((d)[1]), "+f"((d)[2]), "+f"((d)[3]) \
        : "r"(a0), "r"(a1), "r"(a2), "r"(a3), "r"(b0), "r"(b1))

// ---------------- scratch (device globals) --------------------------------
__device__ __align__(128) __nv_bfloat16 g_Ab[NPTS*KE2];    // im2col A [p][hi144|lo144]
__device__ __align__(128) __nv_bfloat16 g_Bb[NOC*KE2];     // weights  [oc][hi144|lo144]
__device__ __align__(128) float g_votes[NPTS*NOC];         // conv output [pt][oc]
__device__ __align__(128) float g_sumAtt[NPTS*OD];
__device__ __align__(128) float g_pmax[NPTS*OD];
__device__ __align__(128) float g_pmean[NPTS*OD];
__device__ __align__(128) float g_gate[NPTS*OD];
__device__ float g_psumArr[1024*8];
__device__ float g_pssArr[1024*8];
__device__ float g_bnMu[8];
__device__ float g_bnRstd[8];

// ---------------- kernel: prep B (split Wt -> bf16 [oc][288]) -------------
__global__ void k_prepB(const float* __restrict__ Wt) {
    int idx = blockIdx.x * 256 + threadIdx.x;   // 1152 blocks exact (294912)
    int oc = idx / KE2, e = idx % KE2;
    int t = e / KDIM, k = e - t*KDIM;
    float w = Wt[oc*KDIM + k];
    float hi = __bfloat162float(__float2bfloat16_rn(w));
    float v = t ? (w - hi) : hi;
    g_Bb[idx] = __float2bfloat16_rn(v);
}

// ---------------- kernel: prep A (im2col + split -> bf16 [p][288]) --------
__global__ __launch_bounds__(256) void k_prepA(const float* __restrict__ caps) {
    extern __shared__ char dyn_sm[];
    float* raw = (float*)dyn_sm;                   // 2048 f
    uint32_t* outp = (uint32_t*)(dyn_sm + 8192);   // [64][145] u32
    int tid = threadIdx.x;
    int m064 = blockIdx.x * 64;
    int b = m064 >> 10;
    int y0 = (m064 & 1023) >> 5;
    for (int i = tid; i < 2048; i += 256) {
        int din = i >> 7, rem = i & 127, yy = y0 - 1 + (rem >> 5), x = rem & 31;
        raw[i] = ((unsigned)yy < 32u) ? caps[b*16384 + din*1024 + yy*32 + x] : 0.f;
    }
    __syncthreads();
    int p = tid & 63, part = tid >> 6;
    int y_local = p >> 5, x = p & 31;
    bool isLo = part >= 2;
    int j0 = (part & 1) * 36;
    for (int j = j0; j < j0 + 36; j++) {
        float v[2];
#pragma unroll
        for (int q = 0; q < 2; q++) {
            int k = 2*j + q;
            int din = k / 9, r = k - din*9;
            int ry = r / 3;
            int xx = x + (r - ry*3) - 1;
            v[q] = ((unsigned)xx < 32u) ? raw[din*128 + (y_local + ry)*32 + xx] : 0.f;
        }
        uint32_t u;
        if (!isLo) {
            __nv_bfloat162 h2 = __float22bfloat162_rn(make_float2(v[0], v[1]));
            memcpy(&u, &h2, 4);
            outp[p*145 + j] = u;
        } else {
            float h0 = __bfloat162float(__float2bfloat16_rn(v[0]));
            float h1 = __bfloat162float(__float2bfloat16_rn(v[1]));
            __nv_bfloat162 l2 = __float22bfloat162_rn(make_float2(v[0]-h0, v[1]-h1));
            memcpy(&u, &l2, 4);
            outp[p*145 + 72 + j] = u;
        }
    }
    __syncthreads();
    uint32_t* gdst = (uint32_t*)((char*)g_Ab + (size_t)m064 * (KE2*2));
    for (int i = tid; i < 64*144; i += 256)
        gdst[i] = outp[(i/144)*145 + (i%144)];
}

// ---------------- kernel: bf16 mma.sync GEMM votes = A x B^T + bias -------
// BM=256, BN=128, 512 threads (4M x 4N warps), 3 MMAs per K16 chunk,
// 3-stage cp.async. (proven R8 configuration)
#define STG 15360
__device__ __forceinline__ void gload(uint32_t dbase, const char* Asrc,
                                      const char* Bsrc, int c, int tid) {
#pragma unroll
    for (int i = 0; i < 2; i++) {
        int q = i*512 + tid;
        int row = q >> 2, part = q & 3;
        uint32_t dst = dbase + row*80 + ((part < 2) ? 0 : 32) + (part & 1)*16;
        CP_ASYNC16(dst, Asrc + (size_t)row*576 + ((part < 2) ? 0 : 288) + c*32 + (part & 1)*16);
    }
    {
        int row = tid >> 2, part = tid & 3;
        uint32_t dst = dbase + 20480 + row*80 + ((part < 2) ? 0 : 32) + (part & 1)*16;
        CP_ASYNC16(dst, Bsrc + (size_t)row*576 + ((part < 2) ? 0 : 288) + c*32 + (part & 1)*16);
    }
}

__global__ __launch_bounds__(512, 1) void k_gemm(const float* __restrict__ bt) {
    extern __shared__ char dyn_sm[];
    __nv_bfloat16* gsm = (__nv_bfloat16*)dyn_sm;
    float* bias_s = (float*)(gsm + 3*STG);
    const int tid = threadIdx.x;
    const int lane = tid & 31;
    const int wid = tid >> 5;
    const int warpM = wid & 3;
    const int warpN = wid >> 2;
    const int n0 = blockIdx.x * 128;
    const int m0 = blockIdx.y * 256;
    if (tid < 128) bias_s[tid] = bt[n0 + tid];

    const char* Asrc = (const char*)g_Ab + (size_t)m0 * (KE2*2);
    const char* Bsrc = (const char*)g_Bb + (size_t)n0 * (KE2*2);
    const uint32_t sb = smem_u32(gsm);

    gload(sb,           Asrc, Bsrc, 0, tid); CP_COMMIT();
    gload(sb + STG*2,   Asrc, Bsrc, 1, tid); CP_COMMIT();

    float acc[4][4][4];
#pragma unroll
    for (int a = 0; a < 4; a++)
#pragma unroll
        for (int b = 0; b < 4; b++)
#pragma unroll
            for (int c = 0; c < 4; c++) acc[a][b][c] = 0.f;

    const int qr = lane >> 2;
    const int qc = lane & 3;
    const int cb = qc*2;

    for (int c = 0; c < 9; c++) {
        if (c == 8) asm volatile("cp.async.wait_group 0;" ::: "memory");
        else        asm volatile("cp.async.wait_group 1;" ::: "memory");
        __syncthreads();
        if (c + 2 < 9) {
            gload(sb + ((c+2)%3)*STG*2, Asrc, Bsrc, c+2, tid);
            CP_COMMIT();
        }
        const __nv_bfloat16* Sa  = gsm + (c%3)*STG;
        const __nv_bfloat16* Sb2 = Sa + 10240;

        uint32_t ah[4][4], bh[4][2], bl[4][2];
#pragma unroll
        for (int mf = 0; mf < 4; mf++) {
            int r = warpM*64 + mf*16 + qr;
            ah[mf][0] = *(const uint32_t*)&Sa[r*40 + cb];
            ah[mf][1] = *(const uint32_t*)&Sa[(r+8)*40 + cb];
            ah[mf][2] = *(const uint32_t*)&Sa[r*40 + cb + 8];
            ah[mf][3] = *(const uint32_t*)&Sa[(r+8)*40 + cb + 8];
        }
#pragma unroll
        for (int nf = 0; nf < 4; nf++) {
            int n = warpN*32 + nf*8 + qr;
            bh[nf][0] = *(const uint32_t*)&Sb2[n*40 + cb];
            bh[nf][1] = *(const uint32_t*)&Sb2[n*40 + cb + 8];
            bl[nf][0] = *(const uint32_t*)&Sb2[n*40 + cb + 16];
            bl[nf][1] = *(const uint32_t*)&Sb2[n*40 + cb + 24];
        }
#pragma unroll
        for (int mf = 0; mf < 4; mf++)
#pragma unroll
            for (int nf = 0; nf < 4; nf++) {
                MMA16816(acc[mf][nf], ah[mf][0], ah[mf][1], ah[mf][2], ah[mf][3],
                         bh[nf][0], bh[nf][1]);
                MMA16816(acc[mf][nf], ah[mf][0], ah[mf][1], ah[mf][2], ah[mf][3],
                         bl[nf][0], bl[nf][1]);
            }
#pragma unroll
        for (int mf = 0; mf < 4; mf++) {
            int r = warpM*64 + mf*16 + qr;
            uint32_t al0 = *(const uint32_t*)&Sa[r*40 + cb + 16];
            uint32_t al1 = *(const uint32_t*)&Sa[(r+8)*40 + cb + 16];
            uint32_t al2 = *(const uint32_t*)&Sa[r*40 + cb + 24];
            uint32_t al3 = *(const uint32_t*)&Sa[(r+8)*40 + cb + 24];
#pragma unroll
            for (int nf = 0; nf < 4; nf++)
                MMA16816(acc[mf][nf], al0, al1, al2, al3, bh[nf][0], bh[nf][1]);
        }
    }

#pragma unroll
    for (int mf = 0; mf < 4; mf++) {
        int row0 = m0 + warpM*64 + mf*16 + qr;
#pragma unroll
        for (int nf = 0; nf < 4; nf++) {
            int cl = warpN*32 + nf*8 + qc*2;
            float b0 = bias_s[cl], b1 = bias_s[cl + 1];
            float2 o0 = make_float2(acc[mf][nf][0] + b0, acc[mf][nf][1] + b1);
            float2 o1 = make_float2(acc[mf][nf][2] + b0, acc[mf][nf][3] + b1);
            *(float2*)(g_votes + (size_t)row0*1024 + n0 + cl) = o0;
            *(float2*)(g_votes + (size_t)(row0+8)*1024 + n0 + cl) = o1;
        }
    }
}

// ---------------- kernel 2: values + pooling + agreement routing ----------
// 64 threads per point; each thread owns one (o, d-pair). Dual 4-deep ffma2
// chains (v0/v1) halve the RAW dependency depth per m.
__global__ __launch_bounds__(256) void k_route(const float* __restrict__ Wv,
                                               const float* __restrict__ bv) {
    __shared__ __align__(16) float wv_s[2048];
    __shared__ float bv_s[256];
    int tid = threadIdx.x;
    for (int i = tid; i < 2048; i += 256) wv_s[i] = Wv[i];
    if (tid < 256) bv_s[tid] = bv[tid];
    __syncthreads();

    int pt  = blockIdx.x * 4 + (tid >> 6);
    int l64 = tid & 63;
    int o   = l64 >> 3;
    const float* vp = g_votes + (size_t)pt * 1024 + l64 * 2;

    u64 vt2[8];
#pragma unroll
    for (int c = 0; c < 8; c++)
        vt2[c] = *(const u64*)(vp + c*128);

    float av[2] = {0.f, 0.f};
    float wsum[2] = {0.f, 0.f};
    float pmax[2] = {-1e30f, -1e30f};
    u64 psum2 = 0ULL;

    const float4* wv4 = (const float4*)wv_s;
#pragma unroll
    for (int c2 = 0; c2 < 8; c2++) {
        u64 ks = 0ULL, kq = 0ULL;
#pragma unroll
        for (int kp = 0; kp < 4; kp++) {
            int m = kp*8 + c2;
            float4 wa = wv4[(o*32 + m)*2 + 0];
            float4 wb = wv4[(o*32 + m)*2 + 1];
            float bvv = bv_s[o*32 + m];
            u64 v0 = pack2(bvv, bvv), v1 = 0ULL, w;
            w = pack2(wa.x, wa.x); v0 = ffma2(w, vt2[0], v0);
            w = pack2(wa.y, wa.y); v1 = ffma2(w, vt2[1], v1);
            w = pack2(wa.z, wa.z); v0 = ffma2(w, vt2[2], v0);
            w = pack2(wa.w, wa.w); v1 = ffma2(w, vt2[3], v1);
            w = pack2(wb.x, wb.x); v0 = ffma2(w, vt2[4], v0);
            w = pack2(wb.y, wb.y); v1 = ffma2(w, vt2[5], v1);
            w = pack2(wb.z, wb.z); v0 = ffma2(w, vt2[6], v0);
            w = pack2(wb.w, wb.w); v1 = ffma2(w, vt2[7], v1);
            u64 v = fadd2(v0, v1);
            ks = fadd2(ks, v);
            kq = ffma2(v, v, kq);
            psum2 = fadd2(psum2, v);
            float f0, f1;
            unpack2(v, f0, f1);
            pmax[0] = fmaxf(pmax[0], f0);
            pmax[1] = fmaxf(pmax[1], f1);
        }
        float ksf0, ksf1, kqf0, kqf1;
        unpack2(ks, ksf0, ksf1);
        unpack2(kq, kqf0, kqf1);
        {
            float mu  = ksf0 * 0.25f;
            float var = fmaxf(kqf0 * 0.25f - mu*mu, 1e-30f);
            float rs  = rsqrtf(var);
            av[0] += mu * rs; wsum[0] += rs;
        }
        {
            float mu  = ksf1 * 0.25f;
            float var = fmaxf(kqf1 * 0.25f - mu*mu, 1e-30f);
            float rs  = rsqrtf(var);
            av[1] += mu * rs; wsum[1] += rs;
        }
    }

    float pf0, pf1;
    unpack2(psum2, pf0, pf1);
    size_t off = (size_t)pt*128 + l64*2;
    *(float2*)(g_sumAtt + off) = make_float2(av[0]/wsum[0], av[1]/wsum[1]);
    *(float2*)(g_pmax   + off) = make_float2(pmax[0], pmax[1]);
    *(float2*)(g_pmean  + off) = make_float2(pf0 * (1.f/32.f), pf1 * (1.f/32.f));
}

// ---------------- kernel 3: 3D gate conv (3x3x3, pad1) + BN partials -----
// (proven R5/R8 layout: thread = (pt, o), 16 d in registers)
__global__ __launch_bounds__(256) void k_gate(const float* __restrict__ Ws) {
    __shared__ float ws_s[54];
    __shared__ float bsum[8], bss[8];
    int tid = threadIdx.x;
    if (tid < 54) ws_s[tid] = Ws[tid];
    if (tid < 8) { bsum[tid] = 0.f; bss[tid] = 0.f; }
    __syncthreads();

    int pt = blockIdx.x * 32 + (tid >> 3);
    int o  = tid & 7;
    int b  = pt >> 10, yx = pt & 1023;
    int y  = yx >> 5,  x  = yx & 31;

    float acc[16];
#pragma unroll
    for (int d = 0; d < 16; d++) acc[d] = 0.f;

    for (int dy = -1; dy <= 1; dy++) {
        int yy = y + dy;
        if ((unsigned)yy >= 32u) continue;
        for (int dx = -1; dx <= 1; dx++) {
            int xx = x + dx;
            if ((unsigned)xx >= 32u) continue;
            int base = ((b << 10) + (yy << 5) + xx)*128 + (o << 4);
            const float4* pm = (const float4*)(g_pmax  + base);
            const float4* pn = (const float4*)(g_pmean + base);
            float rmx[16], rmn[16];
#pragma unroll
            for (int q = 0; q < 4; q++) {
                float4 a = pm[q]; float4 c = pn[q];
                rmx[q*4+0] = a.x; rmx[q*4+1] = a.y; rmx[q*4+2] = a.z; rmx[q*4+3] = a.w;
                rmn[q*4+0] = c.x; rmn[q*4+1] = c.y; rmn[q*4+2] = c.z; rmn[q*4+3] = c.w;
            }
            int wo = (dy+1)*3 + (dx+1);
#pragma unroll
            for (int kz = 0; kz < 3; kz++) {
                float wm = ws_s[kz*9 + wo];
                float wn = ws_s[27 + kz*9 + wo];
#pragma unroll
                for (int d = 0; d < 16; d++) {
                    int s = d + kz - 1;
                    if (s >= 0 && s < 16) acc[d] += wm*rmx[s] + wn*rmn[s];
                }
            }
        }
    }
    float* gp = g_gate + (size_t)pt*128 + (o << 4);
#pragma unroll
    for (int q = 0; q < 4; q++)
        *(float4*)(gp + q*4) = make_float4(acc[q*4+0], acc[q*4+1], acc[q*4+2], acc[q*4+3]);

    float s1 = 0.f, s2 = 0.f;
#pragma unroll
    for (int d = 0; d < 16; d++) { s1 += acc[d]; s2 += acc[d]*acc[d]; }
    s1 += __shfl_xor_sync(0xffffffffu, s1, 8);
    s2 += __shfl_xor_sync(0xffffffffu, s2, 8);
    s1 += __shfl_xor_sync(0xffffffffu, s1, 16);
    s2 += __shfl_xor_sync(0xffffffffu, s2, 16);
    if ((tid & 31) < 8) { atomicAdd(&bsum[o], s1); atomicAdd(&bss[o], s2); }
    __syncthreads();
    if (tid < 8) {
        g_psumArr[blockIdx.x*8 + tid] = bsum[tid];
        g_pssArr [blockIdx.x*8 + tid] = bss[tid];
    }
}

// ---------------- kernel 3b: BN stats finalize (1024 partials) ------------
__global__ void k_bnstats() {
    __shared__ float ss1[256], ss2[256];
    int tid = threadIdx.x;
    int o = tid & 7, seg = tid >> 3;
    float a = 0.f, c = 0.f;
    for (int i = seg*32; i < seg*32 + 32; i++) {
        a += g_psumArr[i*8 + o];
        c += g_pssArr [i*8 + o];
    }
    ss1[tid] = a; ss2[tid] = c;
    __syncthreads();
    if (tid < 8) {
        float A = 0.f, C = 0.f;
        for (int s = 0; s < 32; s++) { A += ss1[s*8 + tid]; C += ss2[s*8 + tid]; }
        const float inv = 1.f / 524288.f;
        float mu = A * inv;
        float var = C * inv - mu*mu;
        g_bnMu[tid]   = mu;
        g_bnRstd[tid] = rsqrtf(var + EPSV);
    }
}

// ---------------- kernel 4: gate apply + LayerNorm + transpose out -------
#define SM4_STRIDE 1025
__global__ __launch_bounds__(256) void k_final(const float* __restrict__ bn_gamma,
                                               const float* __restrict__ bn_beta,
                                               const float* __restrict__ ln_gamma,
                                               const float* __restrict__ ln_beta,
                                               float* __restrict__ out) {
    extern __shared__ char dyn_sm[];
    float* sm4 = (float*)dyn_sm;
    const int RED = 16*SM4_STRIDE;
    int tid = threadIdx.x;
    int b = blockIdx.x & 31;
    int o = blockIdx.x >> 5;
    float mu = g_bnMu[o], rstd = g_bnRstd[o];
    float gam = bn_gamma[0], bet = bn_beta[0];

    int d   = tid & 15;
    int yxb = tid >> 4;
    const float* gp = g_gate   + (b << 10)*128 + (o << 4) + d;
    const float* sp = g_sumAtt + (b << 10)*128 + (o << 4) + d;
    float s = 0.f, ss = 0.f;
    for (int i = 0; i < 64; i++) {
        int yx = yxb + i*16;
        float gg = gp[yx*128];
        float sa = sp[yx*128];
        float z  = (gg - mu) * rstd * gam + bet;
        float sc = 1.f / (1.f + expf(-z));
        float cn = (1.f + sc) * sa;
        sm4[d*SM4_STRIDE + yx] = cn;
        s += cn; ss += cn*cn;
    }
#pragma unroll
    for (int off = 16; off >= 1; off >>= 1) {
        s  += __shfl_xor_sync(0xffffffffu, s,  off);
        ss += __shfl_xor_sync(0xffffffffu, ss, off);
    }
    int wid = tid >> 5;
    if ((tid & 31) == 0) { sm4[RED + wid] = s; sm4[RED + 8 + wid] = ss; }
    __syncthreads();
    if (tid == 0) {
        float S = 0.f, Q = 0.f;
        for (int w = 0; w < 8; w++) { S += sm4[RED + w]; Q += sm4[RED + 8 + w]; }
        const float inv = 1.f / 16384.f;
        float m = S * inv;
        float var = Q * inv - m*m;
        sm4[RED + 16] = m;
        sm4[RED + 17] = rsqrtf(var + EPSV);
    }
    __syncthreads();
    float m = sm4[RED + 16], r = sm4[RED + 17];
    float* ob = out + ((o*32 + b) << 14);
    for (int i = 0; i < 64; i++) {
        int idx = i*256 + tid;
        float v = sm4[(idx >> 10)*SM4_STRIDE + (idx & 1023)];
        ob[idx] = (v - m) * r * ln_gamma[idx] + ln_beta[idx];
    }
}

// ---------------- launch ------------------------------------------------
extern "C" void kernel_launch(void* const* d_in, const int* in_sizes, int n_in,
                              void* d_out, int out_size) {
    const float* caps = (const float*)d_in[0];
    const float* Wt   = (const float*)d_in[1];
    const float* bt   = (const float*)d_in[2];
    const float* Wv   = (const float*)d_in[3];
    const float* bv   = (const float*)d_in[4];
    const float* Ws   = (const float*)d_in[5];
    const float* bng  = (const float*)d_in[6];
    const float* bnb  = (const float*)d_in[7];
    const float* lng  = (const float*)d_in[8];
    const float* lnb  = (const float*)d_in[9];
    float* out = (float*)d_out;

    const int smemA = 8192 + 64*145*4;            // 45312
    const int smemG = 3*STG*2 + 512;              // 92672
    const int smem4 = (16*SM4_STRIDE + 32) * 4;
    cudaFuncSetAttribute(k_prepA, cudaFuncAttributeMaxDynamicSharedMemorySize, smemA);
    cudaFuncSetAttribute(k_gemm,  cudaFuncAttributeMaxDynamicSharedMemorySize, smemG);
    cudaFuncSetAttribute(k_final, cudaFuncAttributeMaxDynamicSharedMemorySize, smem4);

    k_prepB<<<1152, 256>>>(Wt);
    k_prepA<<<512, 256, smemA>>>(caps);
    k_gemm<<<dim3(8, 128), 512, smemG>>>(bt);
    k_route<<<NPTS/4, 256>>>(Wv, bv);
    k_gate<<<NPTS/32, 256>>>(Ws);
    k_bnstats<<<1, 256>>>();
    k_final<<<256, 256, smem4>>>(bng, bnb, lng, lnb, out);
}

// round 13
// speedup vs baseline: 2.1597x; 1.0625x over previous
#include <cuda_runtime.h>
#include <cuda_fp16.h>
#include <math.h>
#include <stdint.h>
#include <string.h>

// Problem constants
#define BATCH 32
#define CIN   8
#define COUT  8
#define KP    4
#define DIN   16
#define DOUT  16
#define SS_   32
#define EPSV  1e-5f

#define NPTS  (BATCH*SS_*SS_)      // 32768 spatial points (b,y,x)
#define NOC   (CIN*COUT*DOUT)      // 1024 conv output channels
#define KDIM  144                  // GEMM K (fp32)
#define KE2   288                  // [hi(144) | lo(144)] fp16 layout
#define OD    (COUT*DOUT)          // 128 (o,d) pairs per point

typedef unsigned long long u64;

// ---------------- packed f32x2 helpers ------------------------------------
__device__ __forceinline__ u64 pack2(float lo, float hi) {
    u64 d; asm("mov.b64 %0,{%1,%2};" : "=l"(d) : "f"(lo), "f"(hi)); return d;
}
__device__ __forceinline__ u64 ffma2(u64 a, u64 b, u64 c) {
    u64 d; asm("fma.rn.f32x2 %0,%1,%2,%3;" : "=l"(d) : "l"(a), "l"(b), "l"(c)); return d;
}
__device__ __forceinline__ u64 fadd2(u64 a, u64 b) {
    u64 d; asm("add.rn.f32x2 %0,%1,%2;" : "=l"(d) : "l"(a), "l"(b)); return d;
}
__device__ __forceinline__ void unpack2(u64 d, float& lo, float& hi) {
    asm("mov.b64 {%0,%1},%2;" : "=f"(lo), "=f"(hi) : "l"(d));
}

__device__ __forceinline__ uint32_t smem_u32(const void* p) {
    uint32_t a;
    asm("{ .reg .u64 t; cvta.to.shared.u64 t, %1; cvt.u32.u64 %0, t; }" : "=r"(a) : "l"(p));
    return a;
}
#define CP_ASYNC16(dst, src) asm volatile("cp.async.cg.shared.global [%0], [%1], 16;" :: "r"(dst), "l"(src))
#define CP_COMMIT()          asm volatile("cp.async.commit_group;" ::: "memory")

#define MMAF16(d, a0, a1, a2, a3, b0, b1) \
    asm volatile("mma.sync.aligned.m16n8k16.row.col.f32.f16.f16.f32 " \
        "{%0,%1,%2,%3},{%4,%5,%6,%7},{%8,%9},{%0,%1,%2,%3};" \
        : "+f"((d)[0]), "+f"((d)[1]), "+f"((d)[2]), "+f"((d)[3]) \
        : "r"(a0), "r"(a1), "r"(a2), "r"(a3), "r"(b0), "r"(b1))

// ---------------- scratch (device globals) --------------------------------
__device__ __align__(128) __half g_Ab[NPTS*KE2];    // im2col A [p][hi144|lo144]
__device__ __align__(128) __half g_Bb[NOC*KE2];     // weights  [oc][hi144|lo144]
__device__ __align__(128) float g_votes[NPTS*NOC];  // conv output [pt][oc]
__device__ __align__(128) float g_sumAtt[NPTS*OD];
__device__ __align__(128) float g_pmax[NPTS*OD];
__device__ __align__(128) float g_pmean[NPTS*OD];
__device__ __align__(128) float g_gate[NPTS*OD];
__device__ float g_psumArr[1024*8];
__device__ float g_pssArr[1024*8];
__device__ float g_bnMu[8];
__device__ float g_bnRstd[8];

// ---------------- kernel: prep B (fp16 split Wt -> [oc][288]) -------------
__global__ void k_prepB(const float* __restrict__ Wt) {
    int idx = blockIdx.x * 256 + threadIdx.x;   // 1152 blocks exact (294912)
    int oc = idx / KE2, e = idx % KE2;
    int t = e / KDIM, k = e - t*KDIM;
    float w = Wt[oc*KDIM + k];
    float hi = __half2float(__float2half_rn(w));
    float v = t ? (w - hi) : hi;
    g_Bb[idx] = __float2half_rn(v);
}

// ---------------- kernel: prep A (im2col + fp16 split -> [p][288]) --------
__global__ __launch_bounds__(256) void k_prepA(const float* __restrict__ caps) {
    extern __shared__ char dyn_sm[];
    float* raw = (float*)dyn_sm;                   // 2048 f
    uint32_t* outp = (uint32_t*)(dyn_sm + 8192);   // [64][145] u32
    int tid = threadIdx.x;
    int m064 = blockIdx.x * 64;
    int b = m064 >> 10;
    int y0 = (m064 & 1023) >> 5;
    for (int i = tid; i < 2048; i += 256) {
        int din = i >> 7, rem = i & 127, yy = y0 - 1 + (rem >> 5), x = rem & 31;
        raw[i] = ((unsigned)yy < 32u) ? caps[b*16384 + din*1024 + yy*32 + x] : 0.f;
    }
    __syncthreads();
    int p = tid & 63, part = tid >> 6;
    int y_local = p >> 5, x = p & 31;
    bool isLo = part >= 2;
    int j0 = (part & 1) * 36;
    for (int j = j0; j < j0 + 36; j++) {
        float v[2];
#pragma unroll
        for (int q = 0; q < 2; q++) {
            int k = 2*j + q;
            int din = k / 9, r = k - din*9;
            int ry = r / 3;
            int xx = x + (r - ry*3) - 1;
            v[q] = ((unsigned)xx < 32u) ? raw[din*128 + (y_local + ry)*32 + xx] : 0.f;
        }
        uint32_t u;
        if (!isLo) {
            __half2 h2 = __floats2half2_rn(v[0], v[1]);
            memcpy(&u, &h2, 4);
            outp[p*145 + j] = u;
        } else {
            float h0 = __half2float(__float2half_rn(v[0]));
            float h1 = __half2float(__float2half_rn(v[1]));
            __half2 l2 = __floats2half2_rn(v[0]-h0, v[1]-h1);
            memcpy(&u, &l2, 4);
            outp[p*145 + 72 + j] = u;
        }
    }
    __syncthreads();
    uint32_t* gdst = (uint32_t*)((char*)g_Ab + (size_t)m064 * (KE2*2));
    for (int i = tid; i < 64*144; i += 256)
        gdst[i] = outp[(i/144)*145 + (i%144)];
}

// ---------------- kernel: fp16 mma.sync GEMM votes = A x B^T + bias -------
// BM=256, BN=128, 512 threads (4M x 4N warps), 2 MMA terms per K16 chunk
// (Ahi·Bhi + Alo·Bhi; Ahi·Blo dropped ~2^-12), 3-stage cp.async.
#define STG 15360
__device__ __forceinline__ void gload(uint32_t dbase, const char* Asrc,
                                      const char* Bsrc, int c, int tid) {
#pragma unroll
    for (int i = 0; i < 2; i++) {
        int q = i*512 + tid;
        int row = q >> 2, part = q & 3;
        uint32_t dst = dbase + row*80 + ((part < 2) ? 0 : 32) + (part & 1)*16;
        CP_ASYNC16(dst, Asrc + (size_t)row*576 + ((part < 2) ? 0 : 288) + c*32 + (part & 1)*16);
    }
    {
        int row = tid >> 2, part = tid & 3;
        uint32_t dst = dbase + 20480 + row*80 + ((part < 2) ? 0 : 32) + (part & 1)*16;
        CP_ASYNC16(dst, Bsrc + (size_t)row*576 + ((part < 2) ? 0 : 288) + c*32 + (part & 1)*16);
    }
}

__global__ __launch_bounds__(512, 1) void k_gemm(const float* __restrict__ bt) {
    extern __shared__ char dyn_sm[];
    __half* gsm = (__half*)dyn_sm;
    float* bias_s = (float*)(gsm + 3*STG);
    const int tid = threadIdx.x;
    const int lane = tid & 31;
    const int wid = tid >> 5;
    const int warpM = wid & 3;
    const int warpN = wid >> 2;
    const int n0 = blockIdx.x * 128;
    const int m0 = blockIdx.y * 256;
    if (tid < 128) bias_s[tid] = bt[n0 + tid];

    const char* Asrc = (const char*)g_Ab + (size_t)m0 * (KE2*2);
    const char* Bsrc = (const char*)g_Bb + (size_t)n0 * (KE2*2);
    const uint32_t sb = smem_u32(gsm);

    gload(sb,           Asrc, Bsrc, 0, tid); CP_COMMIT();
    gload(sb + STG*2,   Asrc, Bsrc, 1, tid); CP_COMMIT();

    float acc[4][4][4];
#pragma unroll
    for (int a = 0; a < 4; a++)
#pragma unroll
        for (int b = 0; b < 4; b++)
#pragma unroll
            for (int c = 0; c < 4; c++) acc[a][b][c] = 0.f;

    const int qr = lane >> 2;
    const int qc = lane & 3;
    const int cb = qc*2;

    for (int c = 0; c < 9; c++) {
        if (c == 8) asm volatile("cp.async.wait_group 0;" ::: "memory");
        else        asm volatile("cp.async.wait_group 1;" ::: "memory");
        __syncthreads();
        if (c + 2 < 9) {
            gload(sb + ((c+2)%3)*STG*2, Asrc, Bsrc, c+2, tid);
            CP_COMMIT();
        }
        const __half* Sa  = gsm + (c%3)*STG;
        const __half* Sb2 = Sa + 10240;

        uint32_t ah[4][4], bh[4][2];
#pragma unroll
        for (int mf = 0; mf < 4; mf++) {
            int r = warpM*64 + mf*16 + qr;
            ah[mf][0] = *(const uint32_t*)&Sa[r*40 + cb];
            ah[mf][1] = *(const uint32_t*)&Sa[(r+8)*40 + cb];
            ah[mf][2] = *(const uint32_t*)&Sa[r*40 + cb + 8];
            ah[mf][3] = *(const uint32_t*)&Sa[(r+8)*40 + cb + 8];
        }
#pragma unroll
        for (int nf = 0; nf < 4; nf++) {
            int n = warpN*32 + nf*8 + qr;
            bh[nf][0] = *(const uint32_t*)&Sb2[n*40 + cb];
            bh[nf][1] = *(const uint32_t*)&Sb2[n*40 + cb + 8];
        }
#pragma unroll
        for (int mf = 0; mf < 4; mf++)
#pragma unroll
            for (int nf = 0; nf < 4; nf++)
                MMAF16(acc[mf][nf], ah[mf][0], ah[mf][1], ah[mf][2], ah[mf][3],
                       bh[nf][0], bh[nf][1]);
#pragma unroll
        for (int mf = 0; mf < 4; mf++) {
            int r = warpM*64 + mf*16 + qr;
            uint32_t al0 = *(const uint32_t*)&Sa[r*40 + cb + 16];
            uint32_t al1 = *(const uint32_t*)&Sa[(r+8)*40 + cb + 16];
            uint32_t al2 = *(const uint32_t*)&Sa[r*40 + cb + 24];
            uint32_t al3 = *(const uint32_t*)&Sa[(r+8)*40 + cb + 24];
#pragma unroll
            for (int nf = 0; nf < 4; nf++)
                MMAF16(acc[mf][nf], al0, al1, al2, al3, bh[nf][0], bh[nf][1]);
        }
    }

#pragma unroll
    for (int mf = 0; mf < 4; mf++) {
        int row0 = m0 + warpM*64 + mf*16 + qr;
#pragma unroll
        for (int nf = 0; nf < 4; nf++) {
            int cl = warpN*32 + nf*8 + qc*2;
            float b0 = bias_s[cl], b1 = bias_s[cl + 1];
            float2 o0 = make_float2(acc[mf][nf][0] + b0, acc[mf][nf][1] + b1);
            float2 o1 = make_float2(acc[mf][nf][2] + b0, acc[mf][nf][3] + b1);
            *(float2*)(g_votes + (size_t)row0*1024 + n0 + cl) = o0;
            *(float2*)(g_votes + (size_t)(row0+8)*1024 + n0 + cl) = o1;
        }
    }
}

// ---------------- kernel 2: values + pooling + agreement routing ----------
__global__ __launch_bounds__(256) void k_route(const float* __restrict__ Wv,
                                               const float* __restrict__ bv) {
    __shared__ __align__(16) float wv_s[2048];
    __shared__ float bv_s[256];
    int tid = threadIdx.x;
    for (int i = tid; i < 2048; i += 256) wv_s[i] = Wv[i];
    if (tid < 256) bv_s[tid] = bv[tid];
    __syncthreads();

    int pt  = blockIdx.x * 4 + (tid >> 6);
    int l64 = tid & 63;
    int o   = l64 >> 3;
    const float* vp = g_votes + (size_t)pt * 1024 + l64 * 2;

    u64 vt2[8];
#pragma unroll
    for (int c = 0; c < 8; c++)
        vt2[c] = *(const u64*)(vp + c*128);

    float av[2] = {0.f, 0.f};
    float wsum[2] = {0.f, 0.f};
    float pmax[2] = {-1e30f, -1e30f};
    u64 psum2 = 0ULL;

    const float4* wv4 = (const float4*)wv_s;
#pragma unroll
    for (int c2 = 0; c2 < 8; c2++) {
        u64 ks = 0ULL, kq = 0ULL;
#pragma unroll
        for (int kp = 0; kp < 4; kp++) {
            int m = kp*8 + c2;
            float4 wa = wv4[(o*32 + m)*2 + 0];
            float4 wb = wv4[(o*32 + m)*2 + 1];
            float bvv = bv_s[o*32 + m];
            u64 v0 = pack2(bvv, bvv), v1 = 0ULL, w;
            w = pack2(wa.x, wa.x); v0 = ffma2(w, vt2[0], v0);
            w = pack2(wa.y, wa.y); v1 = ffma2(w, vt2[1], v1);
            w = pack2(wa.z, wa.z); v0 = ffma2(w, vt2[2], v0);
            w = pack2(wa.w, wa.w); v1 = ffma2(w, vt2[3], v1);
            w = pack2(wb.x, wb.x); v0 = ffma2(w, vt2[4], v0);
            w = pack2(wb.y, wb.y); v1 = ffma2(w, vt2[5], v1);
            w = pack2(wb.z, wb.z); v0 = ffma2(w, vt2[6], v0);
            w = pack2(wb.w, wb.w); v1 = ffma2(w, vt2[7], v1);
            u64 v = fadd2(v0, v1);
            ks = fadd2(ks, v);
            kq = ffma2(v, v, kq);
            psum2 = fadd2(psum2, v);
            float f0, f1;
            unpack2(v, f0, f1);
            pmax[0] = fmaxf(pmax[0], f0);
            pmax[1] = fmaxf(pmax[1], f1);
        }
        float ksf0, ksf1, kqf0, kqf1;
        unpack2(ks, ksf0, ksf1);
        unpack2(kq, kqf0, kqf1);
        {
            float mu  = ksf0 * 0.25f;
            float var = fmaxf(kqf0 * 0.25f - mu*mu, 1e-30f);
            float rs  = rsqrtf(var);
            av[0] += mu * rs; wsum[0] += rs;
        }
        {
            float mu  = ksf1 * 0.25f;
            float var = fmaxf(kqf1 * 0.25f - mu*mu, 1e-30f);
            float rs  = rsqrtf(var);
            av[1] += mu * rs; wsum[1] += rs;
        }
    }

    float pf0, pf1;
    unpack2(psum2, pf0, pf1);
    size_t off = (size_t)pt*128 + l64*2;
    *(float2*)(g_sumAtt + off) = make_float2(av[0]/wsum[0], av[1]/wsum[1]);
    *(float2*)(g_pmax   + off) = make_float2(pmax[0], pmax[1]);
    *(float2*)(g_pmean  + off) = make_float2(pf0 * (1.f/32.f), pf1 * (1.f/32.f));
}

// ---------------- kernel 3: 3D gate conv (3x3x3, pad1) + BN partials -----
__global__ __launch_bounds__(256) void k_gate(const float* __restrict__ Ws) {
    __shared__ float ws_s[54];
    __shared__ float bsum[8], bss[8];
    int tid = threadIdx.x;
    if (tid < 54) ws_s[tid] = Ws[tid];
    if (tid < 8) { bsum[tid] = 0.f; bss[tid] = 0.f; }
    __syncthreads();

    int pt = blockIdx.x * 32 + (tid >> 3);
    int o  = tid & 7;
    int b  = pt >> 10, yx = pt & 1023;
    int y  = yx >> 5,  x  = yx & 31;

    float acc[16];
#pragma unroll
    for (int d = 0; d < 16; d++) acc[d] = 0.f;

    for (int dy = -1; dy <= 1; dy++) {
        int yy = y + dy;
        if ((unsigned)yy >= 32u) continue;
        for (int dx = -1; dx <= 1; dx++) {
            int xx = x + dx;
            if ((unsigned)xx >= 32u) continue;
            int base = ((b << 10) + (yy << 5) + xx)*128 + (o << 4);
            const float4* pm = (const float4*)(g_pmax  + base);
            const float4* pn = (const float4*)(g_pmean + base);
            float rmx[16], rmn[16];
#pragma unroll
            for (int q = 0; q < 4; q++) {
                float4 a = pm[q]; float4 c = pn[q];
                rmx[q*4+0] = a.x; rmx[q*4+1] = a.y; rmx[q*4+2] = a.z; rmx[q*4+3] = a.w;
                rmn[q*4+0] = c.x; rmn[q*4+1] = c.y; rmn[q*4+2] = c.z; rmn[q*4+3] = c.w;
            }
            int wo = (dy+1)*3 + (dx+1);
#pragma unroll
            for (int kz = 0; kz < 3; kz++) {
                float wm = ws_s[kz*9 + wo];
                float wn = ws_s[27 + kz*9 + wo];
#pragma unroll
                for (int d = 0; d < 16; d++) {
                    int s = d + kz - 1;
                    if (s >= 0 && s < 16) acc[d] += wm*rmx[s] + wn*rmn[s];
                }
            }
        }
    }
    float* gp = g_gate + (size_t)pt*128 + (o << 4);
#pragma unroll
    for (int q = 0; q < 4; q++)
        *(float4*)(gp + q*4) = make_float4(acc[q*4+0], acc[q*4+1], acc[q*4+2], acc[q*4+3]);

    float s1 = 0.f, s2 = 0.f;
#pragma unroll
    for (int d = 0; d < 16; d++) { s1 += acc[d]; s2 += acc[d]*acc[d]; }
    s1 += __shfl_xor_sync(0xffffffffu, s1, 8);
    s2 += __shfl_xor_sync(0xffffffffu, s2, 8);
    s1 += __shfl_xor_sync(0xffffffffu, s1, 16);
    s2 += __shfl_xor_sync(0xffffffffu, s2, 16);
    if ((tid & 31) < 8) { atomicAdd(&bsum[o], s1); atomicAdd(&bss[o], s2); }
    __syncthreads();
    if (tid < 8) {
        g_psumArr[blockIdx.x*8 + tid] = bsum[tid];
        g_pssArr [blockIdx.x*8 + tid] = bss[tid];
    }
}

// ---------------- kernel 3b: BN stats finalize (1024 partials) ------------
__global__ void k_bnstats() {
    __shared__ float ss1[256], ss2[256];
    int tid = threadIdx.x;
    int o = tid & 7, seg = tid >> 3;
    float a = 0.f, c = 0.f;
    for (int i = seg*32; i < seg*32 + 32; i++) {
        a += g_psumArr[i*8 + o];
        c += g_pssArr [i*8 + o];
    }
    ss1[tid] = a; ss2[tid] = c;
    __syncthreads();
    if (tid < 8) {
        float A = 0.f, C = 0.f;
        for (int s = 0; s < 32; s++) { A += ss1[s*8 + tid]; C += ss2[s*8 + tid]; }
        const float inv = 1.f / 524288.f;
        float mu = A * inv;
        float var = C * inv - mu*mu;
        g_bnMu[tid]   = mu;
        g_bnRstd[tid] = rsqrtf(var + EPSV);
    }
}

// ---------------- kernel 4: gate apply + LayerNorm + transpose out -------
#define SM4_STRIDE 1025
__global__ __launch_bounds__(256) void k_final(const float* __restrict__ bn_gamma,
                                               const float* __restrict__ bn_beta,
                                               const float* __restrict__ ln_gamma,
                                               const float* __restrict__ ln_beta,
                                               float* __restrict__ out) {
    extern __shared__ char dyn_sm[];
    float* sm4 = (float*)dyn_sm;
    const int RED = 16*SM4_STRIDE;
    int tid = threadIdx.x;
    int b = blockIdx.x & 31;
    int o = blockIdx.x >> 5;
    float mu = g_bnMu[o], rstd = g_bnRstd[o];
    float gam = bn_gamma[0], bet = bn_beta[0];

    int d   = tid & 15;
    int yxb = tid >> 4;
    const float* gp = g_gate   + (b << 10)*128 + (o << 4) + d;
    const float* sp = g_sumAtt + (b << 10)*128 + (o << 4) + d;
    float s = 0.f, ss = 0.f;
    for (int i = 0; i < 64; i++) {
        int yx = yxb + i*16;
        float gg = gp[yx*128];
        float sa = sp[yx*128];
        float z  = (gg - mu) * rstd * gam + bet;
        float sc = 1.f / (1.f + expf(-z));
        float cn = (1.f + sc) * sa;
        sm4[d*SM4_STRIDE + yx] = cn;
        s += cn; ss += cn*cn;
    }
#pragma unroll
    for (int off = 16; off >= 1; off >>= 1) {
        s  += __shfl_xor_sync(0xffffffffu, s,  off);
        ss += __shfl_xor_sync(0xffffffffu, ss, off);
    }
    int wid = tid >> 5;
    if ((tid & 31) == 0) { sm4[RED + wid] = s; sm4[RED + 8 + wid] = ss; }
    __syncthreads();
    if (tid == 0) {
        float S = 0.f, Q = 0.f;
        for (int w = 0; w < 8; w++) { S += sm4[RED + w]; Q += sm4[RED + 8 + w]; }
        const float inv = 1.f / 16384.f;
        float m = S * inv;
        float var = Q * inv - m*m;
        sm4[RED + 16] = m;
        sm4[RED + 17] = rsqrtf(var + EPSV);
    }
    __syncthreads();
    float m = sm4[RED + 16], r = sm4[RED + 17];
    float* ob = out + ((o*32 + b) << 14);
    for (int i = 0; i < 64; i++) {
        int idx = i*256 + tid;
        float v = sm4[(idx >> 10)*SM4_STRIDE + (idx & 1023)];
        ob[idx] = (v - m) * r * ln_gamma[idx] + ln_beta[idx];
    }
}

// ---------------- launch ------------------------------------------------
extern "C" void kernel_launch(void* const* d_in, const int* in_sizes, int n_in,
                              void* d_out, int out_size) {
    const float* caps = (const float*)d_in[0];
    const float* Wt   = (const float*)d_in[1];
    const float* bt   = (const float*)d_in[2];
    const float* Wv   = (const float*)d_in[3];
    const float* bv   = (const float*)d_in[4];
    const float* Ws   = (const float*)d_in[5];
    const float* bng  = (const float*)d_in[6];
    const float* bnb  = (const float*)d_in[7];
    const float* lng  = (const float*)d_in[8];
    const float* lnb  = (const float*)d_in[9];
    float* out = (float*)d_out;

    const int smemA = 8192 + 64*145*4;            // 45312
    const int smemG = 3*STG*2 + 512;              // 92672
    const int smem4 = (16*SM4_STRIDE + 32) * 4;
    cudaFuncSetAttribute(k_prepA, cudaFuncAttributeMaxDynamicSharedMemorySize, smemA);
    cudaFuncSetAttribute(k_gemm,  cudaFuncAttributeMaxDynamicSharedMemorySize, smemG);
    cudaFuncSetAttribute(k_final, cudaFuncAttributeMaxDynamicSharedMemorySize, smem4);

    k_prepB<<<1152, 256>>>(Wt);
    k_prepA<<<512, 256, smemA>>>(caps);
    k_gemm<<<dim3(8, 128), 512, smemG>>>(bt);
    k_route<<<NPTS/4, 256>>>(Wv, bv);
    k_gate<<<NPTS/32, 256>>>(Ws);
    k_bnstats<<<1, 256>>>();
    k_final<<<256, 256, smem4>>>(bng, bnb, lng, lnb, out);
}

// round 14
// speedup vs baseline: 2.1771x; 1.0080x over previous
#include <cuda_runtime.h>
#include <cuda_fp16.h>
#include <math.h>
#include <stdint.h>
#include <string.h>

// Problem constants
#define BATCH 32
#define CIN   8
#define COUT  8
#define KP    4
#define DIN   16
#define DOUT  16
#define SS_   32
#define EPSV  1e-5f

#define NPTS  (BATCH*SS_*SS_)      // 32768 spatial points (b,y,x)
#define NOC   (CIN*COUT*DOUT)      // 1024 conv output channels
#define KDIM  144                  // GEMM K (fp32)
#define KE2   288                  // [hi(144) | lo(144)] fp16 layout
#define OD    (COUT*DOUT)          // 128 (o,d) pairs per point

typedef unsigned long long u64;

// ---------------- packed f32x2 helpers ------------------------------------
__device__ __forceinline__ u64 pack2(float lo, float hi) {
    u64 d; asm("mov.b64 %0,{%1,%2};" : "=l"(d) : "f"(lo), "f"(hi)); return d;
}
__device__ __forceinline__ u64 ffma2(u64 a, u64 b, u64 c) {
    u64 d; asm("fma.rn.f32x2 %0,%1,%2,%3;" : "=l"(d) : "l"(a), "l"(b), "l"(c)); return d;
}
__device__ __forceinline__ u64 fadd2(u64 a, u64 b) {
    u64 d; asm("add.rn.f32x2 %0,%1,%2;" : "=l"(d) : "l"(a), "l"(b)); return d;
}
__device__ __forceinline__ void unpack2(u64 d, float& lo, float& hi) {
    asm("mov.b64 {%0,%1},%2;" : "=f"(lo), "=f"(hi) : "l"(d));
}

__device__ __forceinline__ uint32_t smem_u32(const void* p) {
    uint32_t a;
    asm("{ .reg .u64 t; cvta.to.shared.u64 t, %1; cvt.u32.u64 %0, t; }" : "=r"(a) : "l"(p));
    return a;
}
#define CP_ASYNC16(dst, src) asm volatile("cp.async.cg.shared.global [%0], [%1], 16;" :: "r"(dst), "l"(src))
#define CP_COMMIT()          asm volatile("cp.async.commit_group;" ::: "memory")

#define MMAF16(d, a0, a1, a2, a3, b0, b1) \
    asm volatile("mma.sync.aligned.m16n8k16.row.col.f32.f16.f16.f32 " \
        "{%0,%1,%2,%3},{%4,%5,%6,%7},{%8,%9},{%0,%1,%2,%3};" \
        : "+f"((d)[0]), "+f"((d)[1]), "+f"((d)[2]), "+f"((d)[3]) \
        : "r"(a0), "r"(a1), "r"(a2), "r"(a3), "r"(b0), "r"(b1))

// ---------------- scratch (device globals) --------------------------------
__device__ __align__(128) __half g_Ab[NPTS*KE2];    // im2col A [p][hi144|lo144]
__device__ __align__(128) __half g_Bb[NOC*KE2];     // weights  [oc][hi144|lo144]
__device__ __align__(128) float g_votes[NPTS*NOC];  // conv output [pt][oc]
__device__ __align__(128) float g_sumAtt[NPTS*OD];
__device__ __align__(128) float g_pmax[NPTS*OD];
__device__ __align__(128) float g_pmean[NPTS*OD];
__device__ __align__(128) float g_gate[NPTS*OD];
__device__ float g_psumArr[1024*8];
__device__ float g_pssArr[1024*8];
__device__ float g_bnMu[8];
__device__ float g_bnRstd[8];

// ---------------- kernel: prep B (fp16 split Wt -> [oc][288]) -------------
__global__ void k_prepB(const float* __restrict__ Wt) {
    int idx = blockIdx.x * 256 + threadIdx.x;   // 1152 blocks exact (294912)
    int oc = idx / KE2, e = idx % KE2;
    int t = e / KDIM, k = e - t*KDIM;
    float w = Wt[oc*KDIM + k];
    float hi = __half2float(__float2half_rn(w));
    float v = t ? (w - hi) : hi;
    g_Bb[idx] = __float2half_rn(v);
}

// ---------------- kernel: prep A (im2col + fp16 split -> [p][288]) --------
__global__ __launch_bounds__(256) void k_prepA(const float* __restrict__ caps) {
    extern __shared__ char dyn_sm[];
    float* raw = (float*)dyn_sm;                   // 2048 f
    uint32_t* outp = (uint32_t*)(dyn_sm + 8192);   // [64][145] u32
    int tid = threadIdx.x;
    int m064 = blockIdx.x * 64;
    int b = m064 >> 10;
    int y0 = (m064 & 1023) >> 5;
    for (int i = tid; i < 2048; i += 256) {
        int din = i >> 7, rem = i & 127, yy = y0 - 1 + (rem >> 5), x = rem & 31;
        raw[i] = ((unsigned)yy < 32u) ? caps[b*16384 + din*1024 + yy*32 + x] : 0.f;
    }
    __syncthreads();
    int p = tid & 63, part = tid >> 6;
    int y_local = p >> 5, x = p & 31;
    bool isLo = part >= 2;
    int j0 = (part & 1) * 36;
    for (int j = j0; j < j0 + 36; j++) {
        float v[2];
#pragma unroll
        for (int q = 0; q < 2; q++) {
            int k = 2*j + q;
            int din = k / 9, r = k - din*9;
            int ry = r / 3;
            int xx = x + (r - ry*3) - 1;
            v[q] = ((unsigned)xx < 32u) ? raw[din*128 + (y_local + ry)*32 + xx] : 0.f;
        }
        uint32_t u;
        if (!isLo) {
            __half2 h2 = __floats2half2_rn(v[0], v[1]);
            memcpy(&u, &h2, 4);
            outp[p*145 + j] = u;
        } else {
            float h0 = __half2float(__float2half_rn(v[0]));
            float h1 = __half2float(__float2half_rn(v[1]));
            __half2 l2 = __floats2half2_rn(v[0]-h0, v[1]-h1);
            memcpy(&u, &l2, 4);
            outp[p*145 + 72 + j] = u;
        }
    }
    __syncthreads();
    uint32_t* gdst = (uint32_t*)((char*)g_Ab + (size_t)m064 * (KE2*2));
    for (int i = tid; i < 64*144; i += 256)
        gdst[i] = outp[(i/144)*145 + (i%144)];
}

// ---------------- kernel: persistent fp16 GEMM votes = A x B^T + bias -----
// 148 blocks (one wave), each loops over its tiles with a continuous 3-stage
// cp.async pipeline across tile boundaries. BM=256, BN=128, 512 threads,
// 2 MMA terms per K16 (Ahi·Bhi + Alo·Bhi). B-lo never loaded.
#define STG 15360
#define NTILES 1024    // (8 n) x (128 m)
__device__ __forceinline__ void gloadG(uint32_t dbase, int g, int bid, int tid) {
    int tt = g / 9, c = g - tt*9;
    int t  = bid + 148*tt;
    const char* Asrc = (const char*)g_Ab + (size_t)((t >> 3)*256) * 576;
    const char* Bsrc = (const char*)g_Bb + (size_t)((t & 7)*128) * 576;
#pragma unroll
    for (int i = 0; i < 2; i++) {
        int q = i*512 + tid;
        int row = q >> 2, part = q & 3;
        uint32_t dst = dbase + row*80 + ((part < 2) ? 0 : 32) + (part & 1)*16;
        CP_ASYNC16(dst, Asrc + (size_t)row*576 + ((part < 2) ? 0 : 288) + c*32 + (part & 1)*16);
    }
    if ((tid & 3) < 2) {               // B: hi only
        int row = tid >> 2, part = tid & 1;
        uint32_t dst = dbase + 20480 + row*80 + part*16;
        CP_ASYNC16(dst, Bsrc + (size_t)row*576 + c*32 + part*16);
    }
}

__global__ __launch_bounds__(512, 1) void k_gemm(const float* __restrict__ bt) {
    extern __shared__ char dyn_sm[];
    __half* gsm = (__half*)dyn_sm;
    const int tid = threadIdx.x;
    const int lane = tid & 31;
    const int wid = tid >> 5;
    const int warpM = wid & 3;
    const int warpN = wid >> 2;
    const int bid = blockIdx.x;
    const uint32_t sb = smem_u32(gsm);

    const int nt = (NTILES - bid + 147) / 148;   // tiles for this block
    const int G  = nt * 9;

    gloadG(sb,          0, bid, tid); CP_COMMIT();
    gloadG(sb + STG*2,  1, bid, tid); CP_COMMIT();

    float acc[4][4][4];
#pragma unroll
    for (int a = 0; a < 4; a++)
#pragma unroll
        for (int b = 0; b < 4; b++)
#pragma unroll
            for (int c = 0; c < 4; c++) acc[a][b][c] = 0.f;

    const int qr = lane >> 2;
    const int qc = lane & 3;
    const int cb = qc*2;

    for (int g = 0; g < G; g++) {
        if (g == G-1) asm volatile("cp.async.wait_group 0;" ::: "memory");
        else          asm volatile("cp.async.wait_group 1;" ::: "memory");
        __syncthreads();
        if (g + 2 < G) {
            gloadG(sb + ((g+2)%3)*STG*2, g+2, bid, tid);
            CP_COMMIT();
        }
        const __half* Sa  = gsm + (g%3)*STG;
        const __half* Sb2 = Sa + 10240;

        uint32_t ah[4][4], bh[4][2];
#pragma unroll
        for (int mf = 0; mf < 4; mf++) {
            int r = warpM*64 + mf*16 + qr;
            ah[mf][0] = *(const uint32_t*)&Sa[r*40 + cb];
            ah[mf][1] = *(const uint32_t*)&Sa[(r+8)*40 + cb];
            ah[mf][2] = *(const uint32_t*)&Sa[r*40 + cb + 8];
            ah[mf][3] = *(const uint32_t*)&Sa[(r+8)*40 + cb + 8];
        }
#pragma unroll
        for (int nf = 0; nf < 4; nf++) {
            int n = warpN*32 + nf*8 + qr;
            bh[nf][0] = *(const uint32_t*)&Sb2[n*40 + cb];
            bh[nf][1] = *(const uint32_t*)&Sb2[n*40 + cb + 8];
        }
#pragma unroll
        for (int mf = 0; mf < 4; mf++)
#pragma unroll
            for (int nf = 0; nf < 4; nf++)
                MMAF16(acc[mf][nf], ah[mf][0], ah[mf][1], ah[mf][2], ah[mf][3],
                       bh[nf][0], bh[nf][1]);
#pragma unroll
        for (int mf = 0; mf < 4; mf++) {
            int r = warpM*64 + mf*16 + qr;
            uint32_t al0 = *(const uint32_t*)&Sa[r*40 + cb + 16];
            uint32_t al1 = *(const uint32_t*)&Sa[(r+8)*40 + cb + 16];
            uint32_t al2 = *(const uint32_t*)&Sa[r*40 + cb + 24];
            uint32_t al3 = *(const uint32_t*)&Sa[(r+8)*40 + cb + 24];
#pragma unroll
            for (int nf = 0; nf < 4; nf++)
                MMAF16(acc[mf][nf], al0, al1, al2, al3, bh[nf][0], bh[nf][1]);
        }

        if ((g % 9) == 8) {
            // tile epilogue: bias from gmem (L2-cached), no smem, no sync
            int t  = bid + 148*(g/9);
            int m0 = (t >> 3)*256;
            int n0 = (t & 7)*128;
#pragma unroll
            for (int mf = 0; mf < 4; mf++) {
                int row0 = m0 + warpM*64 + mf*16 + qr;
#pragma unroll
                for (int nf = 0; nf < 4; nf++) {
                    int cl = warpN*32 + nf*8 + qc*2;
                    float2 bb = *(const float2*)(bt + n0 + cl);
                    float2 o0 = make_float2(acc[mf][nf][0] + bb.x, acc[mf][nf][1] + bb.y);
                    float2 o1 = make_float2(acc[mf][nf][2] + bb.x, acc[mf][nf][3] + bb.y);
                    *(float2*)(g_votes + (size_t)row0*1024 + n0 + cl) = o0;
                    *(float2*)(g_votes + (size_t)(row0+8)*1024 + n0 + cl) = o1;
                    acc[mf][nf][0] = 0.f; acc[mf][nf][1] = 0.f;
                    acc[mf][nf][2] = 0.f; acc[mf][nf][3] = 0.f;
                }
            }
        }
    }
}

// ---------------- kernel 2: values + pooling + agreement routing ----------
__global__ __launch_bounds__(256) void k_route(const float* __restrict__ Wv,
                                               const float* __restrict__ bv) {
    __shared__ __align__(16) float wv_s[2048];
    __shared__ float bv_s[256];
    int tid = threadIdx.x;
    for (int i = tid; i < 2048; i += 256) wv_s[i] = Wv[i];
    if (tid < 256) bv_s[tid] = bv[tid];
    __syncthreads();

    int pt  = blockIdx.x * 4 + (tid >> 6);
    int l64 = tid & 63;
    int o   = l64 >> 3;
    const float* vp = g_votes + (size_t)pt * 1024 + l64 * 2;

    u64 vt2[8];
#pragma unroll
    for (int c = 0; c < 8; c++)
        vt2[c] = *(const u64*)(vp + c*128);

    float av[2] = {0.f, 0.f};
    float wsum[2] = {0.f, 0.f};
    float pmax[2] = {-1e30f, -1e30f};
    u64 psum2 = 0ULL;

    const float4* wv4 = (const float4*)wv_s;
#pragma unroll
    for (int c2 = 0; c2 < 8; c2++) {
        u64 ks = 0ULL, kq = 0ULL;
#pragma unroll
        for (int kp = 0; kp < 4; kp++) {
            int m = kp*8 + c2;
            float4 wa = wv4[(o*32 + m)*2 + 0];
            float4 wb = wv4[(o*32 + m)*2 + 1];
            float bvv = bv_s[o*32 + m];
            u64 v0 = pack2(bvv, bvv), v1 = 0ULL, w;
            w = pack2(wa.x, wa.x); v0 = ffma2(w, vt2[0], v0);
            w = pack2(wa.y, wa.y); v1 = ffma2(w, vt2[1], v1);
            w = pack2(wa.z, wa.z); v0 = ffma2(w, vt2[2], v0);
            w = pack2(wa.w, wa.w); v1 = ffma2(w, vt2[3], v1);
            w = pack2(wb.x, wb.x); v0 = ffma2(w, vt2[4], v0);
            w = pack2(wb.y, wb.y); v1 = ffma2(w, vt2[5], v1);
            w = pack2(wb.z, wb.z); v0 = ffma2(w, vt2[6], v0);
            w = pack2(wb.w, wb.w); v1 = ffma2(w, vt2[7], v1);
            u64 v = fadd2(v0, v1);
            ks = fadd2(ks, v);
            kq = ffma2(v, v, kq);
            psum2 = fadd2(psum2, v);
            float f0, f1;
            unpack2(v, f0, f1);
            pmax[0] = fmaxf(pmax[0], f0);
            pmax[1] = fmaxf(pmax[1], f1);
        }
        float ksf0, ksf1, kqf0, kqf1;
        unpack2(ks, ksf0, ksf1);
        unpack2(kq, kqf0, kqf1);
        {
            float mu  = ksf0 * 0.25f;
            float var = fmaxf(kqf0 * 0.25f - mu*mu, 1e-30f);
            float rs  = rsqrtf(var);
            av[0] += mu * rs; wsum[0] += rs;
        }
        {
            float mu  = ksf1 * 0.25f;
            float var = fmaxf(kqf1 * 0.25f - mu*mu, 1e-30f);
            float rs  = rsqrtf(var);
            av[1] += mu * rs; wsum[1] += rs;
        }
    }

    float pf0, pf1;
    unpack2(psum2, pf0, pf1);
    size_t off = (size_t)pt*128 + l64*2;
    *(float2*)(g_sumAtt + off) = make_float2(av[0]/wsum[0], av[1]/wsum[1]);
    *(float2*)(g_pmax   + off) = make_float2(pmax[0], pmax[1]);
    *(float2*)(g_pmean  + off) = make_float2(pf0 * (1.f/32.f), pf1 * (1.f/32.f));
}

// ---------------- kernel 3: 3D gate conv (3x3x3, pad1) + BN partials -----
__global__ __launch_bounds__(256) void k_gate(const float* __restrict__ Ws) {
    __shared__ float ws_s[54];
    __shared__ float bsum[8], bss[8];
    int tid = threadIdx.x;
    if (tid < 54) ws_s[tid] = Ws[tid];
    if (tid < 8) { bsum[tid] = 0.f; bss[tid] = 0.f; }
    __syncthreads();

    int pt = blockIdx.x * 32 + (tid >> 3);
    int o  = tid & 7;
    int b  = pt >> 10, yx = pt & 1023;
    int y  = yx >> 5,  x  = yx & 31;

    float acc[16];
#pragma unroll
    for (int d = 0; d < 16; d++) acc[d] = 0.f;

    for (int dy = -1; dy <= 1; dy++) {
        int yy = y + dy;
        if ((unsigned)yy >= 32u) continue;
        for (int dx = -1; dx <= 1; dx++) {
            int xx = x + dx;
            if ((unsigned)xx >= 32u) continue;
            int base = ((b << 10) + (yy << 5) + xx)*128 + (o << 4);
            const float4* pm = (const float4*)(g_pmax  + base);
            const float4* pn = (const float4*)(g_pmean + base);
            float rmx[16], rmn[16];
#pragma unroll
            for (int q = 0; q < 4; q++) {
                float4 a = pm[q]; float4 c = pn[q];
                rmx[q*4+0] = a.x; rmx[q*4+1] = a.y; rmx[q*4+2] = a.z; rmx[q*4+3] = a.w;
                rmn[q*4+0] = c.x; rmn[q*4+1] = c.y; rmn[q*4+2] = c.z; rmn[q*4+3] = c.w;
            }
            int wo = (dy+1)*3 + (dx+1);
#pragma unroll
            for (int kz = 0; kz < 3; kz++) {
                float wm = ws_s[kz*9 + wo];
                float wn = ws_s[27 + kz*9 + wo];
#pragma unroll
                for (int d = 0; d < 16; d++) {
                    int s = d + kz - 1;
                    if (s >= 0 && s < 16) acc[d] += wm*rmx[s] + wn*rmn[s];
                }
            }
        }
    }
    float* gp = g_gate + (size_t)pt*128 + (o << 4);
#pragma unroll
    for (int q = 0; q < 4; q++)
        *(float4*)(gp + q*4) = make_float4(acc[q*4+0], acc[q*4+1], acc[q*4+2], acc[q*4+3]);

    float s1 = 0.f, s2 = 0.f;
#pragma unroll
    for (int d = 0; d < 16; d++) { s1 += acc[d]; s2 += acc[d]*acc[d]; }
    s1 += __shfl_xor_sync(0xffffffffu, s1, 8);
    s2 += __shfl_xor_sync(0xffffffffu, s2, 8);
    s1 += __shfl_xor_sync(0xffffffffu, s1, 16);
    s2 += __shfl_xor_sync(0xffffffffu, s2, 16);
    if ((tid & 31) < 8) { atomicAdd(&bsum[o], s1); atomicAdd(&bss[o], s2); }
    __syncthreads();
    if (tid < 8) {
        g_psumArr[blockIdx.x*8 + tid] = bsum[tid];
        g_pssArr [blockIdx.x*8 + tid] = bss[tid];
    }
}

// ---------------- kernel 3b: BN stats finalize (1024 partials) ------------
__global__ void k_bnstats() {
    __shared__ float ss1[256], ss2[256];
    int tid = threadIdx.x;
    int o = tid & 7, seg = tid >> 3;
    float a = 0.f, c = 0.f;
    for (int i = seg*32; i < seg*32 + 32; i++) {
        a += g_psumArr[i*8 + o];
        c += g_pssArr [i*8 + o];
    }
    ss1[tid] = a; ss2[tid] = c;
    __syncthreads();
    if (tid < 8) {
        float A = 0.f, C = 0.f;
        for (int s = 0; s < 32; s++) { A += ss1[s*8 + tid]; C += ss2[s*8 + tid]; }
        const float inv = 1.f / 524288.f;
        float mu = A * inv;
        float var = C * inv - mu*mu;
        g_bnMu[tid]   = mu;
        g_bnRstd[tid] = rsqrtf(var + EPSV);
    }
}

// ---------------- kernel 4: gate apply + LayerNorm + transpose out -------
#define SM4_STRIDE 1025
__global__ __launch_bounds__(256) void k_final(const float* __restrict__ bn_gamma,
                                               const float* __restrict__ bn_beta,
                                               const float* __restrict__ ln_gamma,
                                               const float* __restrict__ ln_beta,
                                               float* __restrict__ out) {
    extern __shared__ char dyn_sm[];
    float* sm4 = (float*)dyn_sm;
    const int RED = 16*SM4_STRIDE;
    int tid = threadIdx.x;
    int b = blockIdx.x & 31;
    int o = blockIdx.x >> 5;
    float mu = g_bnMu[o], rstd = g_bnRstd[o];
    float gam = bn_gamma[0], bet = bn_beta[0];

    int d   = tid & 15;
    int yxb = tid >> 4;
    const float* gp = g_gate   + (b << 10)*128 + (o << 4) + d;
    const float* sp = g_sumAtt + (b << 10)*128 + (o << 4) + d;
    float s = 0.f, ss = 0.f;
    for (int i = 0; i < 64; i++) {
        int yx = yxb + i*16;
        float gg = gp[yx*128];
        float sa = sp[yx*128];
        float z  = (gg - mu) * rstd * gam + bet;
        float sc = 1.f / (1.f + expf(-z));
        float cn = (1.f + sc) * sa;
        sm4[d*SM4_STRIDE + yx] = cn;
        s += cn; ss += cn*cn;
    }
#pragma unroll
    for (int off = 16; off >= 1; off >>= 1) {
        s  += __shfl_xor_sync(0xffffffffu, s,  off);
        ss += __shfl_xor_sync(0xffffffffu, ss, off);
    }
    int wid = tid >> 5;
    if ((tid & 31) == 0) { sm4[RED + wid] = s; sm4[RED + 8 + wid] = ss; }
    __syncthreads();
    if (tid == 0) {
        float S = 0.f, Q = 0.f;
        for (int w = 0; w < 8; w++) { S += sm4[RED + w]; Q += sm4[RED + 8 + w]; }
        const float inv = 1.f / 16384.f;
        float m = S * inv;
        float var = Q * inv - m*m;
        sm4[RED + 16] = m;
        sm4[RED + 17] = rsqrtf(var + EPSV);
    }
    __syncthreads();
    float m = sm4[RED + 16], r = sm4[RED + 17];
    float* ob = out + ((o*32 + b) << 14);
    for (int i = 0; i < 64; i++) {
        int idx = i*256 + tid;
        float v = sm4[(idx >> 10)*SM4_STRIDE + (idx & 1023)];
        ob[idx] = (v - m) * r * ln_gamma[idx] + ln_beta[idx];
    }
}

// ---------------- launch ------------------------------------------------
extern "C" void kernel_launch(void* const* d_in, const int* in_sizes, int n_in,
                              void* d_out, int out_size) {
    const float* caps = (const float*)d_in[0];
    const float* Wt   = (const float*)d_in[1];
    const float* bt   = (const float*)d_in[2];
    const float* Wv   = (const float*)d_in[3];
    const float* bv   = (const float*)d_in[4];
    const float* Ws   = (const float*)d_in[5];
    const float* bng  = (const float*)d_in[6];
    const float* bnb  = (const float*)d_in[7];
    const float* lng  = (const float*)d_in[8];
    const float* lnb  = (const float*)d_in[9];
    float* out = (float*)d_out;

    const int smemA = 8192 + 64*145*4;            // 45312
    const int smemG = 3*STG*2;                    // 92160
    const int smem4 = (16*SM4_STRIDE + 32) * 4;
    cudaFuncSetAttribute(k_prepA, cudaFuncAttributeMaxDynamicSharedMemorySize, smemA);
    cudaFuncSetAttribute(k_gemm,  cudaFuncAttributeMaxDynamicSharedMemorySize, smemG);
    cudaFuncSetAttribute(k_final, cudaFuncAttributeMaxDynamicSharedMemorySize, smem4);

    k_prepB<<<1152, 256>>>(Wt);
    k_prepA<<<512, 256, smemA>>>(caps);
    k_gemm<<<148, 512, smemG>>>(bt);
    k_route<<<NPTS/4, 256>>>(Wv, bv);
    k_gate<<<NPTS/32, 256>>>(Ws);
    k_bnstats<<<1, 256>>>();
    k_final<<<256, 256, smem4>>>(bng, bnb, lng, lnb, out);
}

// round 15
// speedup vs baseline: 2.2073x; 1.0139x over previous
#include <cuda_runtime.h>
#include <cuda_fp16.h>
#include <math.h>
#include <stdint.h>
#include <string.h>

// Problem constants
#define BATCH 32
#define CIN   8
#define COUT  8
#define KP    4
#define DIN   16
#define DOUT  16
#define SS_   32
#define EPSV  1e-5f

#define NPTS  (BATCH*SS_*SS_)      // 32768 spatial points (b,y,x)
#define NOC   (CIN*COUT*DOUT)      // 1024 conv output channels
#define KDIM  144                  // GEMM K (fp32)
#define KE2   288                  // [hi(144) | lo(144)] fp16 layout
#define OD    (COUT*DOUT)          // 128 (o,d) pairs per point

typedef unsigned long long u64;

// ---------------- packed f32x2 helpers ------------------------------------
__device__ __forceinline__ u64 pack2(float lo, float hi) {
    u64 d; asm("mov.b64 %0,{%1,%2};" : "=l"(d) : "f"(lo), "f"(hi)); return d;
}
__device__ __forceinline__ u64 ffma2(u64 a, u64 b, u64 c) {
    u64 d; asm("fma.rn.f32x2 %0,%1,%2,%3;" : "=l"(d) : "l"(a), "l"(b), "l"(c)); return d;
}
__device__ __forceinline__ u64 fadd2(u64 a, u64 b) {
    u64 d; asm("add.rn.f32x2 %0,%1,%2;" : "=l"(d) : "l"(a), "l"(b)); return d;
}
__device__ __forceinline__ void unpack2(u64 d, float& lo, float& hi) {
    asm("mov.b64 {%0,%1},%2;" : "=f"(lo), "=f"(hi) : "l"(d));
}

__device__ __forceinline__ uint32_t smem_u32(const void* p) {
    uint32_t a;
    asm("{ .reg .u64 t; cvta.to.shared.u64 t, %1; cvt.u32.u64 %0, t; }" : "=r"(a) : "l"(p));
    return a;
}
#define CP_ASYNC16(dst, src) asm volatile("cp.async.cg.shared.global [%0], [%1], 16;" :: "r"(dst), "l"(src))
#define CP_COMMIT()          asm volatile("cp.async.commit_group;" ::: "memory")

#define MMAF16(d, a0, a1, a2, a3, b0, b1) \
    asm volatile("mma.sync.aligned.m16n8k16.row.col.f32.f16.f16.f32 " \
        "{%0,%1,%2,%3},{%4,%5,%6,%7},{%8,%9},{%0,%1,%2,%3};" \
        : "+f"((d)[0]), "+f"((d)[1]), "+f"((d)[2]), "+f"((d)[3]) \
        : "r"(a0), "r"(a1), "r"(a2), "r"(a3), "r"(b0), "r"(b1))

// ---------------- scratch (device globals) --------------------------------
__device__ __align__(128) __half g_Ab[NPTS*KE2];    // im2col A [p][hi144|lo144]
__device__ __align__(128) __half g_Bb[NOC*KE2];     // weights  [oc][hi144|lo144]
__device__ __align__(128) __half g_votes[NPTS*NOC]; // conv output, fp16 [pt][oc]
__device__ __align__(128) float g_sumAtt[NPTS*OD];
__device__ __align__(128) float g_pmax[NPTS*OD];
__device__ __align__(128) float g_pmean[NPTS*OD];
__device__ __align__(128) float g_gate[NPTS*OD];
__device__ float g_psumArr[1024*8];
__device__ float g_pssArr[1024*8];
__device__ float g_bnMu[8];
__device__ float g_bnRstd[8];

// ---------------- kernel: prep B (fp16 split Wt -> [oc][288]) -------------
__global__ void k_prepB(const float* __restrict__ Wt) {
    int idx = blockIdx.x * 256 + threadIdx.x;   // 1152 blocks exact (294912)
    int oc = idx / KE2, e = idx % KE2;
    int t = e / KDIM, k = e - t*KDIM;
    float w = Wt[oc*KDIM + k];
    float hi = __half2float(__float2half_rn(w));
    float v = t ? (w - hi) : hi;
    g_Bb[idx] = __float2half_rn(v);
}

// ---------------- kernel: prep A (im2col + fp16 split -> [p][288]) --------
__global__ __launch_bounds__(256) void k_prepA(const float* __restrict__ caps) {
    extern __shared__ char dyn_sm[];
    float* raw = (float*)dyn_sm;                   // 2048 f
    uint32_t* outp = (uint32_t*)(dyn_sm + 8192);   // [64][145] u32
    int tid = threadIdx.x;
    int m064 = blockIdx.x * 64;
    int b = m064 >> 10;
    int y0 = (m064 & 1023) >> 5;
    for (int i = tid; i < 2048; i += 256) {
        int din = i >> 7, rem = i & 127, yy = y0 - 1 + (rem >> 5), x = rem & 31;
        raw[i] = ((unsigned)yy < 32u) ? caps[b*16384 + din*1024 + yy*32 + x] : 0.f;
    }
    __syncthreads();
    int p = tid & 63, part = tid >> 6;
    int y_local = p >> 5, x = p & 31;
    bool isLo = part >= 2;
    int j0 = (part & 1) * 36;
    for (int j = j0; j < j0 + 36; j++) {
        float v[2];
#pragma unroll
        for (int q = 0; q < 2; q++) {
            int k = 2*j + q;
            int din = k / 9, r = k - din*9;
            int ry = r / 3;
            int xx = x + (r - ry*3) - 1;
            v[q] = ((unsigned)xx < 32u) ? raw[din*128 + (y_local + ry)*32 + xx] : 0.f;
        }
        uint32_t u;
        if (!isLo) {
            __half2 h2 = __floats2half2_rn(v[0], v[1]);
            memcpy(&u, &h2, 4);
            outp[p*145 + j] = u;
        } else {
            float h0 = __half2float(__float2half_rn(v[0]));
            float h1 = __half2float(__float2half_rn(v[1]));
            __half2 l2 = __floats2half2_rn(v[0]-h0, v[1]-h1);
            memcpy(&u, &l2, 4);
            outp[p*145 + 72 + j] = u;
        }
    }
    __syncthreads();
    uint32_t* gdst = (uint32_t*)((char*)g_Ab + (size_t)m064 * (KE2*2));
    for (int i = tid; i < 64*144; i += 256)
        gdst[i] = outp[(i/144)*145 + (i%144)];
}

// ---------------- kernel: persistent fp16 GEMM votes = A x B^T + bias -----
// 148 blocks (one wave), continuous 3-stage cp.async pipeline across tiles.
// BM=256, BN=128, 512 threads, 2 MMA terms per K16. fp16 votes output.
#define STG 15360
#define NTILES 1024    // (8 n) x (128 m)
__device__ __forceinline__ void gloadG(uint32_t dbase, int g, int bid, int tid) {
    int tt = g / 9, c = g - tt*9;
    int t  = bid + 148*tt;
    const char* Asrc = (const char*)g_Ab + (size_t)((t >> 3)*256) * 576;
    const char* Bsrc = (const char*)g_Bb + (size_t)((t & 7)*128) * 576;
#pragma unroll
    for (int i = 0; i < 2; i++) {
        int q = i*512 + tid;
        int row = q >> 2, part = q & 3;
        uint32_t dst = dbase + row*80 + ((part < 2) ? 0 : 32) + (part & 1)*16;
        CP_ASYNC16(dst, Asrc + (size_t)row*576 + ((part < 2) ? 0 : 288) + c*32 + (part & 1)*16);
    }
    if ((tid & 3) < 2) {               // B: hi only
        int row = tid >> 2, part = tid & 1;
        uint32_t dst = dbase + 20480 + row*80 + part*16;
        CP_ASYNC16(dst, Bsrc + (size_t)row*576 + c*32 + part*16);
    }
}

__global__ __launch_bounds__(512, 1) void k_gemm(const float* __restrict__ bt) {
    extern __shared__ char dyn_sm[];
    __half* gsm = (__half*)dyn_sm;
    const int tid = threadIdx.x;
    const int lane = tid & 31;
    const int wid = tid >> 5;
    const int warpM = wid & 3;
    const int warpN = wid >> 2;
    const int bid = blockIdx.x;
    const uint32_t sb = smem_u32(gsm);

    const int nt = (NTILES - bid + 147) / 148;   // tiles for this block
    const int G  = nt * 9;

    gloadG(sb,          0, bid, tid); CP_COMMIT();
    gloadG(sb + STG*2,  1, bid, tid); CP_COMMIT();

    float acc[4][4][4];
#pragma unroll
    for (int a = 0; a < 4; a++)
#pragma unroll
        for (int b = 0; b < 4; b++)
#pragma unroll
            for (int c = 0; c < 4; c++) acc[a][b][c] = 0.f;

    const int qr = lane >> 2;
    const int qc = lane & 3;
    const int cb = qc*2;

    for (int g = 0; g < G; g++) {
        if (g == G-1) asm volatile("cp.async.wait_group 0;" ::: "memory");
        else          asm volatile("cp.async.wait_group 1;" ::: "memory");
        __syncthreads();
        if (g + 2 < G) {
            gloadG(sb + ((g+2)%3)*STG*2, g+2, bid, tid);
            CP_COMMIT();
        }
        const __half* Sa  = gsm + (g%3)*STG;
        const __half* Sb2 = Sa + 10240;

        uint32_t ah[4][4], bh[4][2];
#pragma unroll
        for (int mf = 0; mf < 4; mf++) {
            int r = warpM*64 + mf*16 + qr;
            ah[mf][0] = *(const uint32_t*)&Sa[r*40 + cb];
            ah[mf][1] = *(const uint32_t*)&Sa[(r+8)*40 + cb];
            ah[mf][2] = *(const uint32_t*)&Sa[r*40 + cb + 8];
            ah[mf][3] = *(const uint32_t*)&Sa[(r+8)*40 + cb + 8];
        }
#pragma unroll
        for (int nf = 0; nf < 4; nf++) {
            int n = warpN*32 + nf*8 + qr;
            bh[nf][0] = *(const uint32_t*)&Sb2[n*40 + cb];
            bh[nf][1] = *(const uint32_t*)&Sb2[n*40 + cb + 8];
        }
#pragma unroll
        for (int mf = 0; mf < 4; mf++)
#pragma unroll
            for (int nf = 0; nf < 4; nf++)
                MMAF16(acc[mf][nf], ah[mf][0], ah[mf][1], ah[mf][2], ah[mf][3],
                       bh[nf][0], bh[nf][1]);
#pragma unroll
        for (int mf = 0; mf < 4; mf++) {
            int r = warpM*64 + mf*16 + qr;
            uint32_t al0 = *(const uint32_t*)&Sa[r*40 + cb + 16];
            uint32_t al1 = *(const uint32_t*)&Sa[(r+8)*40 + cb + 16];
            uint32_t al2 = *(const uint32_t*)&Sa[r*40 + cb + 24];
            uint32_t al3 = *(const uint32_t*)&Sa[(r+8)*40 + cb + 24];
#pragma unroll
            for (int nf = 0; nf < 4; nf++)
                MMAF16(acc[mf][nf], al0, al1, al2, al3, bh[nf][0], bh[nf][1]);
        }

        if ((g % 9) == 8) {
            // tile epilogue: bias from gmem (L2-cached), fp16 stores, no sync
            int t  = bid + 148*(g/9);
            int m0 = (t >> 3)*256;
            int n0 = (t & 7)*128;
#pragma unroll
            for (int mf = 0; mf < 4; mf++) {
                int row0 = m0 + warpM*64 + mf*16 + qr;
#pragma unroll
                for (int nf = 0; nf < 4; nf++) {
                    int cl = warpN*32 + nf*8 + qc*2;
                    float2 bb = *(const float2*)(bt + n0 + cl);
                    __half2 h0 = __floats2half2_rn(acc[mf][nf][0] + bb.x, acc[mf][nf][1] + bb.y);
                    __half2 h1 = __floats2half2_rn(acc[mf][nf][2] + bb.x, acc[mf][nf][3] + bb.y);
                    *(__half2*)(g_votes + (size_t)row0*1024 + n0 + cl) = h0;
                    *(__half2*)(g_votes + (size_t)(row0+8)*1024 + n0 + cl) = h1;
                    acc[mf][nf][0] = 0.f; acc[mf][nf][1] = 0.f;
                    acc[mf][nf][2] = 0.f; acc[mf][nf][3] = 0.f;
                }
            }
        }
    }
}

// ---------------- kernel 2: values + pooling + agreement routing ----------
// 64 threads per point; each thread owns one (o, d-pair). fp16 vote loads
// (half L1/DRAM traffic), fp32 math.
__global__ __launch_bounds__(256) void k_route(const float* __restrict__ Wv,
                                               const float* __restrict__ bv) {
    __shared__ __align__(16) float wv_s[2048];
    __shared__ float bv_s[256];
    int tid = threadIdx.x;
    for (int i = tid; i < 2048; i += 256) wv_s[i] = Wv[i];
    if (tid < 256) bv_s[tid] = bv[tid];
    __syncthreads();

    int pt  = blockIdx.x * 4 + (tid >> 6);
    int l64 = tid & 63;
    int o   = l64 >> 3;
    const __half* vp = g_votes + (size_t)pt * 1024 + l64 * 2;

    u64 vt2[8];
#pragma unroll
    for (int c = 0; c < 8; c++) {
        __half2 h = *(const __half2*)(vp + c*128);
        float2 f = __half22float2(h);
        vt2[c] = pack2(f.x, f.y);
    }

    float av[2] = {0.f, 0.f};
    float wsum[2] = {0.f, 0.f};
    float pmax[2] = {-1e30f, -1e30f};
    u64 psum2 = 0ULL;

    const float4* wv4 = (const float4*)wv_s;
#pragma unroll
    for (int c2 = 0; c2 < 8; c2++) {
        u64 ks = 0ULL, kq = 0ULL;
#pragma unroll
        for (int kp = 0; kp < 4; kp++) {
            int m = kp*8 + c2;
            float4 wa = wv4[(o*32 + m)*2 + 0];
            float4 wb = wv4[(o*32 + m)*2 + 1];
            float bvv = bv_s[o*32 + m];
            u64 v0 = pack2(bvv, bvv), v1 = 0ULL, w;
            w = pack2(wa.x, wa.x); v0 = ffma2(w, vt2[0], v0);
            w = pack2(wa.y, wa.y); v1 = ffma2(w, vt2[1], v1);
            w = pack2(wa.z, wa.z); v0 = ffma2(w, vt2[2], v0);
            w = pack2(wa.w, wa.w); v1 = ffma2(w, vt2[3], v1);
            w = pack2(wb.x, wb.x); v0 = ffma2(w, vt2[4], v0);
            w = pack2(wb.y, wb.y); v1 = ffma2(w, vt2[5], v1);
            w = pack2(wb.z, wb.z); v0 = ffma2(w, vt2[6], v0);
            w = pack2(wb.w, wb.w); v1 = ffma2(w, vt2[7], v1);
            u64 v = fadd2(v0, v1);
            ks = fadd2(ks, v);
            kq = ffma2(v, v, kq);
            psum2 = fadd2(psum2, v);
            float f0, f1;
            unpack2(v, f0, f1);
            pmax[0] = fmaxf(pmax[0], f0);
            pmax[1] = fmaxf(pmax[1], f1);
        }
        float ksf0, ksf1, kqf0, kqf1;
        unpack2(ks, ksf0, ksf1);
        unpack2(kq, kqf0, kqf1);
        {
            float mu  = ksf0 * 0.25f;
            float var = fmaxf(kqf0 * 0.25f - mu*mu, 1e-30f);
            float rs  = rsqrtf(var);
            av[0] += mu * rs; wsum[0] += rs;
        }
        {
            float mu  = ksf1 * 0.25f;
            float var = fmaxf(kqf1 * 0.25f - mu*mu, 1e-30f);
            float rs  = rsqrtf(var);
            av[1] += mu * rs; wsum[1] += rs;
        }
    }

    float pf0, pf1;
    unpack2(psum2, pf0, pf1);
    size_t off = (size_t)pt*128 + l64*2;
    *(float2*)(g_sumAtt + off) = make_float2(av[0]/wsum[0], av[1]/wsum[1]);
    *(float2*)(g_pmax   + off) = make_float2(pmax[0], pmax[1]);
    *(float2*)(g_pmean  + off) = make_float2(pf0 * (1.f/32.f), pf1 * (1.f/32.f));
}

// ---------------- kernel 3: 3D gate conv (3x3x3, pad1) + BN partials -----
__global__ __launch_bounds__(256) void k_gate(const float* __restrict__ Ws) {
    __shared__ float ws_s[54];
    __shared__ float bsum[8], bss[8];
    int tid = threadIdx.x;
    if (tid < 54) ws_s[tid] = Ws[tid];
    if (tid < 8) { bsum[tid] = 0.f; bss[tid] = 0.f; }
    __syncthreads();

    int pt = blockIdx.x * 32 + (tid >> 3);
    int o  = tid & 7;
    int b  = pt >> 10, yx = pt & 1023;
    int y  = yx >> 5,  x  = yx & 31;

    float acc[16];
#pragma unroll
    for (int d = 0; d < 16; d++) acc[d] = 0.f;

    for (int dy = -1; dy <= 1; dy++) {
        int yy = y + dy;
        if ((unsigned)yy >= 32u) continue;
        for (int dx = -1; dx <= 1; dx++) {
            int xx = x + dx;
            if ((unsigned)xx >= 32u) continue;
            int base = ((b << 10) + (yy << 5) + xx)*128 + (o << 4);
            const float4* pm = (const float4*)(g_pmax  + base);
            const float4* pn = (const float4*)(g_pmean + base);
            float rmx[16], rmn[16];
#pragma unroll
            for (int q = 0; q < 4; q++) {
                float4 a = pm[q]; float4 c = pn[q];
                rmx[q*4+0] = a.x; rmx[q*4+1] = a.y; rmx[q*4+2] = a.z; rmx[q*4+3] = a.w;
                rmn[q*4+0] = c.x; rmn[q*4+1] = c.y; rmn[q*4+2] = c.z; rmn[q*4+3] = c.w;
            }
            int wo = (dy+1)*3 + (dx+1);
#pragma unroll
            for (int kz = 0; kz < 3; kz++) {
                float wm = ws_s[kz*9 + wo];
                float wn = ws_s[27 + kz*9 + wo];
#pragma unroll
                for (int d = 0; d < 16; d++) {
                    int s = d + kz - 1;
                    if (s >= 0 && s < 16) acc[d] += wm*rmx[s] + wn*rmn[s];
                }
            }
        }
    }
    float* gp = g_gate + (size_t)pt*128 + (o << 4);
#pragma unroll
    for (int q = 0; q < 4; q++)
        *(float4*)(gp + q*4) = make_float4(acc[q*4+0], acc[q*4+1], acc[q*4+2], acc[q*4+3]);

    float s1 = 0.f, s2 = 0.f;
#pragma unroll
    for (int d = 0; d < 16; d++) { s1 += acc[d]; s2 += acc[d]*acc[d]; }
    s1 += __shfl_xor_sync(0xffffffffu, s1, 8);
    s2 += __shfl_xor_sync(0xffffffffu, s2, 8);
    s1 += __shfl_xor_sync(0xffffffffu, s1, 16);
    s2 += __shfl_xor_sync(0xffffffffu, s2, 16);
    if ((tid & 31) < 8) { atomicAdd(&bsum[o], s1); atomicAdd(&bss[o], s2); }
    __syncthreads();
    if (tid < 8) {
        g_psumArr[blockIdx.x*8 + tid] = bsum[tid];
        g_pssArr [blockIdx.x*8 + tid] = bss[tid];
    }
}

// ---------------- kernel 3b: BN stats finalize (1024 partials) ------------
__global__ void k_bnstats() {
    __shared__ float ss1[256], ss2[256];
    int tid = threadIdx.x;
    int o = tid & 7, seg = tid >> 3;
    float a = 0.f, c = 0.f;
    for (int i = seg*32; i < seg*32 + 32; i++) {
        a += g_psumArr[i*8 + o];
        c += g_pssArr [i*8 + o];
    }
    ss1[tid] = a; ss2[tid] = c;
    __syncthreads();
    if (tid < 8) {
        float A = 0.f, C = 0.f;
        for (int s = 0; s < 32; s++) { A += ss1[s*8 + tid]; C += ss2[s*8 + tid]; }
        const float inv = 1.f / 524288.f;
        float mu = A * inv;
        float var = C * inv - mu*mu;
        g_bnMu[tid]   = mu;
        g_bnRstd[tid] = rsqrtf(var + EPSV);
    }
}

// ---------------- kernel 4: gate apply + LayerNorm + transpose out -------
#define SM4_STRIDE 1025
__global__ __launch_bounds__(256) void k_final(const float* __restrict__ bn_gamma,
                                               const float* __restrict__ bn_beta,
                                               const float* __restrict__ ln_gamma,
                                               const float* __restrict__ ln_beta,
                                               float* __restrict__ out) {
    extern __shared__ char dyn_sm[];
    float* sm4 = (float*)dyn_sm;
    const int RED = 16*SM4_STRIDE;
    int tid = threadIdx.x;
    int b = blockIdx.x & 31;
    int o = blockIdx.x >> 5;
    float mu = g_bnMu[o], rstd = g_bnRstd[o];
    float gam = bn_gamma[0], bet = bn_beta[0];

    int d   = tid & 15;
    int yxb = tid >> 4;
    const float* gp = g_gate   + (b << 10)*128 + (o << 4) + d;
    const float* sp = g_sumAtt + (b << 10)*128 + (o << 4) + d;
    float s = 0.f, ss = 0.f;
    for (int i = 0; i < 64; i++) {
        int yx = yxb + i*16;
        float gg = gp[yx*128];
        float sa = sp[yx*128];
        float z  = (gg - mu) * rstd * gam + bet;
        float sc = 1.f / (1.f + expf(-z));
        float cn = (1.f + sc) * sa;
        sm4[d*SM4_STRIDE + yx] = cn;
        s += cn; ss += cn*cn;
    }
#pragma unroll
    for (int off = 16; off >= 1; off >>= 1) {
        s  += __shfl_xor_sync(0xffffffffu, s,  off);
        ss += __shfl_xor_sync(0xffffffffu, ss, off);
    }
    int wid = tid >> 5;
    if ((tid & 31) == 0) { sm4[RED + wid] = s; sm4[RED + 8 + wid] = ss; }
    __syncthreads();
    if (tid == 0) {
        float S = 0.f, Q = 0.f;
        for (int w = 0; w < 8; w++) { S += sm4[RED + w]; Q += sm4[RED + 8 + w]; }
        const float inv = 1.f / 16384.f;
        float m = S * inv;
        float var = Q * inv - m*m;
        sm4[RED + 16] = m;
        sm4[RED + 17] = rsqrtf(var + EPSV);
    }
    __syncthreads();
    float m = sm4[RED + 16], r = sm4[RED + 17];
    float* ob = out + ((o*32 + b) << 14);
    for (int i = 0; i < 64; i++) {
        int idx = i*256 + tid;
        float v = sm4[(idx >> 10)*SM4_STRIDE + (idx & 1023)];
        ob[idx] = (v - m) * r * ln_gamma[idx] + ln_beta[idx];
    }
}

// ---------------- launch ------------------------------------------------
extern "C" void kernel_launch(void* const* d_in, const int* in_sizes, int n_in,
                              void* d_out, int out_size) {
    const float* caps = (const float*)d_in[0];
    const float* Wt   = (const float*)d_in[1];
    const float* bt   = (const float*)d_in[2];
    const float* Wv   = (const float*)d_in[3];
    const float* bv   = (const float*)d_in[4];
    const float* Ws   = (const float*)d_in[5];
    const float* bng  = (const float*)d_in[6];
    const float* bnb  = (const float*)d_in[7];
    const float* lng  = (const float*)d_in[8];
    const float* lnb  = (const float*)d_in[9];
    float* out = (float*)d_out;

    const int smemA = 8192 + 64*145*4;            // 45312
    const int smemG = 3*STG*2;                    // 92160
    const int smem4 = (16*SM4_STRIDE + 32) * 4;
    cudaFuncSetAttribute(k_prepA, cudaFuncAttributeMaxDynamicSharedMemorySize, smemA);
    cudaFuncSetAttribute(k_gemm,  cudaFuncAttributeMaxDynamicSharedMemorySize, smemG);
    cudaFuncSetAttribute(k_final, cudaFuncAttributeMaxDynamicSharedMemorySize, smem4);

    k_prepB<<<1152, 256>>>(Wt);
    k_prepA<<<512, 256, smemA>>>(caps);
    k_gemm<<<148, 512, smemG>>>(bt);
    k_route<<<NPTS/4, 256>>>(Wv, bv);
    k_gate<<<NPTS/32, 256>>>(Ws);
    k_bnstats<<<1, 256>>>();
    k_final<<<256, 256, smem4>>>(bng, bnb, lng, lnb, out);
}

// round 16
// speedup vs baseline: 2.2976x; 1.0409x over previous
#include <cuda_runtime.h>
#include <cuda_fp16.h>
#include <math.h>
#include <stdint.h>
#include <string.h>

// Problem constants
#define BATCH 32
#define CIN   8
#define COUT  8
#define KP    4
#define DIN   16
#define DOUT  16
#define SS_   32
#define EPSV  1e-5f

#define NPTS  (BATCH*SS_*SS_)      // 32768 spatial points (b,y,x)
#define NOC   (CIN*COUT*DOUT)      // 1024 conv output channels
#define KDIM  144                  // GEMM K (fp32)
#define KE2   288                  // [hi(144) | lo(144)] fp16 layout
#define OD    (COUT*DOUT)          // 128 (o,d) pairs per point

typedef unsigned long long u64;

// ---------------- packed f32x2 helpers ------------------------------------
__device__ __forceinline__ u64 pack2(float lo, float hi) {
    u64 d; asm("mov.b64 %0,{%1,%2};" : "=l"(d) : "f"(lo), "f"(hi)); return d;
}
__device__ __forceinline__ u64 ffma2(u64 a, u64 b, u64 c) {
    u64 d; asm("fma.rn.f32x2 %0,%1,%2,%3;" : "=l"(d) : "l"(a), "l"(b), "l"(c)); return d;
}
__device__ __forceinline__ u64 fadd2(u64 a, u64 b) {
    u64 d; asm("add.rn.f32x2 %0,%1,%2;" : "=l"(d) : "l"(a), "l"(b)); return d;
}
__device__ __forceinline__ void unpack2(u64 d, float& lo, float& hi) {
    asm("mov.b64 {%0,%1},%2;" : "=f"(lo), "=f"(hi) : "l"(d));
}

__device__ __forceinline__ uint32_t smem_u32(const void* p) {
    uint32_t a;
    asm("{ .reg .u64 t; cvta.to.shared.u64 t, %1; cvt.u32.u64 %0, t; }" : "=r"(a) : "l"(p));
    return a;
}
#define CP_ASYNC16(dst, src) asm volatile("cp.async.cg.shared.global [%0], [%1], 16;" :: "r"(dst), "l"(src))
#define CP_COMMIT()          asm volatile("cp.async.commit_group;" ::: "memory")

#define MMAF16(d, a0, a1, a2, a3, b0, b1) \
    asm volatile("mma.sync.aligned.m16n8k16.row.col.f32.f16.f16.f32 " \
        "{%0,%1,%2,%3},{%4,%5,%6,%7},{%8,%9},{%0,%1,%2,%3};" \
        : "+f"((d)[0]), "+f"((d)[1]), "+f"((d)[2]), "+f"((d)[3]) \
        : "r"(a0), "r"(a1), "r"(a2), "r"(a3), "r"(b0), "r"(b1))

// fp16 pack/unpack helpers
__device__ __forceinline__ void unp8(uint4 u, float* o) {
    float2 f;
    f = __half22float2(*(__half2*)&u.x); o[0]=f.x; o[1]=f.y;
    f = __half22float2(*(__half2*)&u.y); o[2]=f.x; o[3]=f.y;
    f = __half22float2(*(__half2*)&u.z); o[4]=f.x; o[5]=f.y;
    f = __half22float2(*(__half2*)&u.w); o[6]=f.x; o[7]=f.y;
}
__device__ __forceinline__ uint4 pk8(const float* a) {
    uint4 u; __half2 h;
    h = __floats2half2_rn(a[0], a[1]); u.x = *(uint32_t*)&h;
    h = __floats2half2_rn(a[2], a[3]); u.y = *(uint32_t*)&h;
    h = __floats2half2_rn(a[4], a[5]); u.z = *(uint32_t*)&h;
    h = __floats2half2_rn(a[6], a[7]); u.w = *(uint32_t*)&h;
    return u;
}

// ---------------- scratch (device globals) --------------------------------
__device__ __align__(128) __half g_Ab[NPTS*KE2];    // im2col A [p][hi144|lo144]
__device__ __align__(128) __half g_Bb[NOC*KE2];     // weights  [oc][hi144|lo144]
__device__ __align__(128) __half g_votes[NPTS*NOC]; // conv output, fp16 [pt][oc]
__device__ __align__(128) float  g_sumAtt[NPTS*OD]; // fp32 (feeds output directly)
__device__ __align__(128) __half g_pmax[NPTS*OD];
__device__ __align__(128) __half g_pmean[NPTS*OD];
__device__ __align__(128) __half g_gate[NPTS*OD];
__device__ float g_psumArr[1024*8];
__device__ float g_pssArr[1024*8];
__device__ float g_bnMu[8];
__device__ float g_bnRstd[8];

// ---------------- kernel: prep B (fp16 split Wt -> [oc][288]) -------------
__global__ void k_prepB(const float* __restrict__ Wt) {
    int idx = blockIdx.x * 256 + threadIdx.x;   // 1152 blocks exact (294912)
    int oc = idx / KE2, e = idx % KE2;
    int t = e / KDIM, k = e - t*KDIM;
    float w = Wt[oc*KDIM + k];
    float hi = __half2float(__float2half_rn(w));
    float v = t ? (w - hi) : hi;
    g_Bb[idx] = __float2half_rn(v);
}

// ---------------- kernel: prep A (im2col + fp16 split -> [p][288]) --------
__global__ __launch_bounds__(256) void k_prepA(const float* __restrict__ caps) {
    extern __shared__ char dyn_sm[];
    float* raw = (float*)dyn_sm;                   // 2048 f
    uint32_t* outp = (uint32_t*)(dyn_sm + 8192);   // [64][145] u32
    int tid = threadIdx.x;
    int m064 = blockIdx.x * 64;
    int b = m064 >> 10;
    int y0 = (m064 & 1023) >> 5;
    for (int i = tid; i < 2048; i += 256) {
        int din = i >> 7, rem = i & 127, yy = y0 - 1 + (rem >> 5), x = rem & 31;
        raw[i] = ((unsigned)yy < 32u) ? caps[b*16384 + din*1024 + yy*32 + x] : 0.f;
    }
    __syncthreads();
    int p = tid & 63, part = tid >> 6;
    int y_local = p >> 5, x = p & 31;
    bool isLo = part >= 2;
    int j0 = (part & 1) * 36;
    for (int j = j0; j < j0 + 36; j++) {
        float v[2];
#pragma unroll
        for (int q = 0; q < 2; q++) {
            int k = 2*j + q;
            int din = k / 9, r = k - din*9;
            int ry = r / 3;
            int xx = x + (r - ry*3) - 1;
            v[q] = ((unsigned)xx < 32u) ? raw[din*128 + (y_local + ry)*32 + xx] : 0.f;
        }
        uint32_t u;
        if (!isLo) {
            __half2 h2 = __floats2half2_rn(v[0], v[1]);
            memcpy(&u, &h2, 4);
            outp[p*145 + j] = u;
        } else {
            float h0 = __half2float(__float2half_rn(v[0]));
            float h1 = __half2float(__float2half_rn(v[1]));
            __half2 l2 = __floats2half2_rn(v[0]-h0, v[1]-h1);
            memcpy(&u, &l2, 4);
            outp[p*145 + 72 + j] = u;
        }
    }
    __syncthreads();
    uint32_t* gdst = (uint32_t*)((char*)g_Ab + (size_t)m064 * (KE2*2));
    for (int i = tid; i < 64*144; i += 256)
        gdst[i] = outp[(i/144)*145 + (i%144)];
}

// ---------------- kernel: persistent fp16 GEMM votes = A x B^T + bias -----
#define STG 15360
#define NTILES 1024    // (8 n) x (128 m)
__device__ __forceinline__ void gloadG(uint32_t dbase, int g, int bid, int tid) {
    int tt = g / 9, c = g - tt*9;
    int t  = bid + 148*tt;
    const char* Asrc = (const char*)g_Ab + (size_t)((t >> 3)*256) * 576;
    const char* Bsrc = (const char*)g_Bb + (size_t)((t & 7)*128) * 576;
#pragma unroll
    for (int i = 0; i < 2; i++) {
        int q = i*512 + tid;
        int row = q >> 2, part = q & 3;
        uint32_t dst = dbase + row*80 + ((part < 2) ? 0 : 32) + (part & 1)*16;
        CP_ASYNC16(dst, Asrc + (size_t)row*576 + ((part < 2) ? 0 : 288) + c*32 + (part & 1)*16);
    }
    if ((tid & 3) < 2) {               // B: hi only
        int row = tid >> 2, part = tid & 1;
        uint32_t dst = dbase + 20480 + row*80 + part*16;
        CP_ASYNC16(dst, Bsrc + (size_t)row*576 + c*32 + part*16);
    }
}

__global__ __launch_bounds__(512, 1) void k_gemm(const float* __restrict__ bt) {
    extern __shared__ char dyn_sm[];
    __half* gsm = (__half*)dyn_sm;
    const int tid = threadIdx.x;
    const int lane = tid & 31;
    const int wid = tid >> 5;
    const int warpM = wid & 3;
    const int warpN = wid >> 2;
    const int bid = blockIdx.x;
    const uint32_t sb = smem_u32(gsm);

    const int nt = (NTILES - bid + 147) / 148;
    const int G  = nt * 9;

    gloadG(sb,          0, bid, tid); CP_COMMIT();
    gloadG(sb + STG*2,  1, bid, tid); CP_COMMIT();

    float acc[4][4][4];
#pragma unroll
    for (int a = 0; a < 4; a++)
#pragma unroll
        for (int b = 0; b < 4; b++)
#pragma unroll
            for (int c = 0; c < 4; c++) acc[a][b][c] = 0.f;

    const int qr = lane >> 2;
    const int qc = lane & 3;
    const int cb = qc*2;

    for (int g = 0; g < G; g++) {
        if (g == G-1) asm volatile("cp.async.wait_group 0;" ::: "memory");
        else          asm volatile("cp.async.wait_group 1;" ::: "memory");
        __syncthreads();
        if (g + 2 < G) {
            gloadG(sb + ((g+2)%3)*STG*2, g+2, bid, tid);
            CP_COMMIT();
        }
        const __half* Sa  = gsm + (g%3)*STG;
        const __half* Sb2 = Sa + 10240;

        uint32_t ah[4][4], bh[4][2];
#pragma unroll
        for (int mf = 0; mf < 4; mf++) {
            int r = warpM*64 + mf*16 + qr;
            ah[mf][0] = *(const uint32_t*)&Sa[r*40 + cb];
            ah[mf][1] = *(const uint32_t*)&Sa[(r+8)*40 + cb];
            ah[mf][2] = *(const uint32_t*)&Sa[r*40 + cb + 8];
            ah[mf][3] = *(const uint32_t*)&Sa[(r+8)*40 + cb + 8];
        }
#pragma unroll
        for (int nf = 0; nf < 4; nf++) {
            int n = warpN*32 + nf*8 + qr;
            bh[nf][0] = *(const uint32_t*)&Sb2[n*40 + cb];
            bh[nf][1] = *(const uint32_t*)&Sb2[n*40 + cb + 8];
        }
#pragma unroll
        for (int mf = 0; mf < 4; mf++)
#pragma unroll
            for (int nf = 0; nf < 4; nf++)
                MMAF16(acc[mf][nf], ah[mf][0], ah[mf][1], ah[mf][2], ah[mf][3],
                       bh[nf][0], bh[nf][1]);
#pragma unroll
        for (int mf = 0; mf < 4; mf++) {
            int r = warpM*64 + mf*16 + qr;
            uint32_t al0 = *(const uint32_t*)&Sa[r*40 + cb + 16];
            uint32_t al1 = *(const uint32_t*)&Sa[(r+8)*40 + cb + 16];
            uint32_t al2 = *(const uint32_t*)&Sa[r*40 + cb + 24];
            uint32_t al3 = *(const uint32_t*)&Sa[(r+8)*40 + cb + 24];
#pragma unroll
            for (int nf = 0; nf < 4; nf++)
                MMAF16(acc[mf][nf], al0, al1, al2, al3, bh[nf][0], bh[nf][1]);
        }

        if ((g % 9) == 8) {
            int t  = bid + 148*(g/9);
            int m0 = (t >> 3)*256;
            int n0 = (t & 7)*128;
#pragma unroll
            for (int mf = 0; mf < 4; mf++) {
                int row0 = m0 + warpM*64 + mf*16 + qr;
#pragma unroll
                for (int nf = 0; nf < 4; nf++) {
                    int cl = warpN*32 + nf*8 + qc*2;
                    float2 bb = *(const float2*)(bt + n0 + cl);
                    __half2 h0 = __floats2half2_rn(acc[mf][nf][0] + bb.x, acc[mf][nf][1] + bb.y);
                    __half2 h1 = __floats2half2_rn(acc[mf][nf][2] + bb.x, acc[mf][nf][3] + bb.y);
                    *(__half2*)(g_votes + (size_t)row0*1024 + n0 + cl) = h0;
                    *(__half2*)(g_votes + (size_t)(row0+8)*1024 + n0 + cl) = h1;
                    acc[mf][nf][0] = 0.f; acc[mf][nf][1] = 0.f;
                    acc[mf][nf][2] = 0.f; acc[mf][nf][3] = 0.f;
                }
            }
        }
    }
}

// ---------------- kernel 2: values + pooling + agreement routing ----------
// 64 threads per point; fp16 vote loads, fp32 math, fp16 pmax/pmean stores.
// psum derived from ksum sums (removed from inner loop).
__global__ __launch_bounds__(256) void k_route(const float* __restrict__ Wv,
                                               const float* __restrict__ bv) {
    __shared__ __align__(16) float wv_s[2048];
    __shared__ float bv_s[256];
    int tid = threadIdx.x;
    for (int i = tid; i < 2048; i += 256) wv_s[i] = Wv[i];
    if (tid < 256) bv_s[tid] = bv[tid];
    __syncthreads();

    int pt  = blockIdx.x * 4 + (tid >> 6);
    int l64 = tid & 63;
    int o   = l64 >> 3;
    const __half* vp = g_votes + (size_t)pt * 1024 + l64 * 2;

    u64 vt2[8];
#pragma unroll
    for (int c = 0; c < 8; c++) {
        __half2 h = *(const __half2*)(vp + c*128);
        float2 f = __half22float2(h);
        vt2[c] = pack2(f.x, f.y);
    }

    float av[2] = {0.f, 0.f};
    float wsum[2] = {0.f, 0.f};
    float pmax[2] = {-1e30f, -1e30f};
    float ps0 = 0.f, ps1 = 0.f;

    const float4* wv4 = (const float4*)wv_s;
#pragma unroll
    for (int c2 = 0; c2 < 8; c2++) {
        u64 ks = 0ULL, kq = 0ULL;
#pragma unroll
        for (int kp = 0; kp < 4; kp++) {
            int m = kp*8 + c2;
            float4 wa = wv4[(o*32 + m)*2 + 0];
            float4 wb = wv4[(o*32 + m)*2 + 1];
            float bvv = bv_s[o*32 + m];
            u64 v0 = pack2(bvv, bvv), v1 = 0ULL, w;
            w = pack2(wa.x, wa.x); v0 = ffma2(w, vt2[0], v0);
            w = pack2(wa.y, wa.y); v1 = ffma2(w, vt2[1], v1);
            w = pack2(wa.z, wa.z); v0 = ffma2(w, vt2[2], v0);
            w = pack2(wa.w, wa.w); v1 = ffma2(w, vt2[3], v1);
            w = pack2(wb.x, wb.x); v0 = ffma2(w, vt2[4], v0);
            w = pack2(wb.y, wb.y); v1 = ffma2(w, vt2[5], v1);
            w = pack2(wb.z, wb.z); v0 = ffma2(w, vt2[6], v0);
            w = pack2(wb.w, wb.w); v1 = ffma2(w, vt2[7], v1);
            u64 v = fadd2(v0, v1);
            ks = fadd2(ks, v);
            kq = ffma2(v, v, kq);
            float f0, f1;
            unpack2(v, f0, f1);
            pmax[0] = fmaxf(pmax[0], f0);
            pmax[1] = fmaxf(pmax[1], f1);
        }
        float ksf0, ksf1, kqf0, kqf1;
        unpack2(ks, ksf0, ksf1);
        unpack2(kq, kqf0, kqf1);
        ps0 += ksf0; ps1 += ksf1;
        {
            float mu  = ksf0 * 0.25f;
            float var = fmaxf(kqf0 * 0.25f - mu*mu, 1e-30f);
            float rs  = rsqrtf(var);
            av[0] += mu * rs; wsum[0] += rs;
        }
        {
            float mu  = ksf1 * 0.25f;
            float var = fmaxf(kqf1 * 0.25f - mu*mu, 1e-30f);
            float rs  = rsqrtf(var);
            av[1] += mu * rs; wsum[1] += rs;
        }
    }

    size_t off = (size_t)pt*128 + l64*2;
    *(float2*)(g_sumAtt + off) = make_float2(av[0]/wsum[0], av[1]/wsum[1]);
    *(__half2*)(g_pmax  + off) = __floats2half2_rn(pmax[0], pmax[1]);
    *(__half2*)(g_pmean + off) = __floats2half2_rn(ps0 * (1.f/32.f), ps1 * (1.f/32.f));
}

// ---------------- kernel 3: 3D gate conv (3x3x3, pad1) + BN partials -----
// (R5 layout: thread = (pt, o), 16 d in registers; fp16 inputs/outputs)
__global__ __launch_bounds__(256) void k_gate(const float* __restrict__ Ws) {
    __shared__ float ws_s[54];
    __shared__ float bsum[8], bss[8];
    int tid = threadIdx.x;
    if (tid < 54) ws_s[tid] = Ws[tid];
    if (tid < 8) { bsum[tid] = 0.f; bss[tid] = 0.f; }
    __syncthreads();

    int pt = blockIdx.x * 32 + (tid >> 3);
    int o  = tid & 7;
    int b  = pt >> 10, yx = pt & 1023;
    int y  = yx >> 5,  x  = yx & 31;

    float acc[16];
#pragma unroll
    for (int d = 0; d < 16; d++) acc[d] = 0.f;

    for (int dy = -1; dy <= 1; dy++) {
        int yy = y + dy;
        if ((unsigned)yy >= 32u) continue;
        for (int dx = -1; dx <= 1; dx++) {
            int xx = x + dx;
            if ((unsigned)xx >= 32u) continue;
            int base = ((b << 10) + (yy << 5) + xx)*128 + (o << 4);
            const uint4* pmx = (const uint4*)(g_pmax  + base);
            const uint4* pmn = (const uint4*)(g_pmean + base);
            float rmx[16], rmn[16];
            unp8(pmx[0], rmx); unp8(pmx[1], rmx + 8);
            unp8(pmn[0], rmn); unp8(pmn[1], rmn + 8);
            int wo = (dy+1)*3 + (dx+1);
#pragma unroll
            for (int kz = 0; kz < 3; kz++) {
                float wm = ws_s[kz*9 + wo];
                float wn = ws_s[27 + kz*9 + wo];
#pragma unroll
                for (int d = 0; d < 16; d++) {
                    int s = d + kz - 1;
                    if (s >= 0 && s < 16) acc[d] += wm*rmx[s] + wn*rmn[s];
                }
            }
        }
    }
    __half* gp = g_gate + (size_t)pt*128 + (o << 4);
    *(uint4*)gp       = pk8(acc);
    *(uint4*)(gp + 8) = pk8(acc + 8);

    float s1 = 0.f, s2 = 0.f;
#pragma unroll
    for (int d = 0; d < 16; d++) { s1 += acc[d]; s2 += acc[d]*acc[d]; }
    s1 += __shfl_xor_sync(0xffffffffu, s1, 8);
    s2 += __shfl_xor_sync(0xffffffffu, s2, 8);
    s1 += __shfl_xor_sync(0xffffffffu, s1, 16);
    s2 += __shfl_xor_sync(0xffffffffu, s2, 16);
    if ((tid & 31) < 8) { atomicAdd(&bsum[o], s1); atomicAdd(&bss[o], s2); }
    __syncthreads();
    if (tid < 8) {
        g_psumArr[blockIdx.x*8 + tid] = bsum[tid];
        g_pssArr [blockIdx.x*8 + tid] = bss[tid];
    }
}

// ---------------- kernel 3b: BN stats finalize (1024 partials) ------------
__global__ void k_bnstats() {
    __shared__ float ss1[256], ss2[256];
    int tid = threadIdx.x;
    int o = tid & 7, seg = tid >> 3;
    float a = 0.f, c = 0.f;
    for (int i = seg*32; i < seg*32 + 32; i++) {
        a += g_psumArr[i*8 + o];
        c += g_pssArr [i*8 + o];
    }
    ss1[tid] = a; ss2[tid] = c;
    __syncthreads();
    if (tid < 8) {
        float A = 0.f, C = 0.f;
        for (int s = 0; s < 32; s++) { A += ss1[s*8 + tid]; C += ss2[s*8 + tid]; }
        const float inv = 1.f / 524288.f;
        float mu = A * inv;
        float var = C * inv - mu*mu;
        g_bnMu[tid]   = mu;
        g_bnRstd[tid] = rsqrtf(var + EPSV);
    }
}

// ---------------- kernel 4: gate apply + LayerNorm + transpose out -------
#define SM4_STRIDE 1025
__global__ __launch_bounds__(256) void k_final(const float* __restrict__ bn_gamma,
                                               const float* __restrict__ bn_beta,
                                               const float* __restrict__ ln_gamma,
                                               const float* __restrict__ ln_beta,
                                               float* __restrict__ out) {
    extern __shared__ char dyn_sm[];
    float* sm4 = (float*)dyn_sm;
    const int RED = 16*SM4_STRIDE;
    int tid = threadIdx.x;
    int b = blockIdx.x & 31;
    int o = blockIdx.x >> 5;
    float mu = g_bnMu[o], rstd = g_bnRstd[o];
    float gam = bn_gamma[0], bet = bn_beta[0];

    int d   = tid & 15;
    int yxb = tid >> 4;
    const __half* gp = g_gate   + (size_t)(b << 10)*128 + (o << 4) + d;
    const float*  sp = g_sumAtt + (size_t)(b << 10)*128 + (o << 4) + d;
    float s = 0.f, ss = 0.f;
    for (int i = 0; i < 64; i++) {
        int yx = yxb + i*16;
        float gg = __half2float(gp[yx*128]);
        float sa = sp[yx*128];
        float z  = (gg - mu) * rstd * gam + bet;
        float sc = 1.f / (1.f + expf(-z));
        float cn = (1.f + sc) * sa;
        sm4[d*SM4_STRIDE + yx] = cn;
        s += cn; ss += cn*cn;
    }
#pragma unroll
    for (int off = 16; off >= 1; off >>= 1) {
        s  += __shfl_xor_sync(0xffffffffu, s,  off);
        ss += __shfl_xor_sync(0xffffffffu, ss, off);
    }
    int wid = tid >> 5;
    if ((tid & 31) == 0) { sm4[RED + wid] = s; sm4[RED + 8 + wid] = ss; }
    __syncthreads();
    if (tid == 0) {
        float S = 0.f, Q = 0.f;
        for (int w = 0; w < 8; w++) { S += sm4[RED + w]; Q += sm4[RED + 8 + w]; }
        const float inv = 1.f / 16384.f;
        float m = S * inv;
        float var = Q * inv - m*m;
        sm4[RED + 16] = m;
        sm4[RED + 17] = rsqrtf(var + EPSV);
    }
    __syncthreads();
    float m = sm4[RED + 16], r = sm4[RED + 17];
    float* ob = out + ((o*32 + b) << 14);
    for (int i = 0; i < 64; i++) {
        int idx = i*256 + tid;
        float v = sm4[(idx >> 10)*SM4_STRIDE + (idx & 1023)];
        ob[idx] = (v - m) * r * ln_gamma[idx] + ln_beta[idx];
    }
}

// ---------------- launch ------------------------------------------------
extern "C" void kernel_launch(void* const* d_in, const int* in_sizes, int n_in,
                              void* d_out, int out_size) {
    const float* caps = (const float*)d_in[0];
    const float* Wt   = (const float*)d_in[1];
    const float* bt   = (const float*)d_in[2];
    const float* Wv   = (const float*)d_in[3];
    const float* bv   = (const float*)d_in[4];
    const float* Ws   = (const float*)d_in[5];
    const float* bng  = (const float*)d_in[6];
    const float* bnb  = (const float*)d_in[7];
    const float* lng  = (const float*)d_in[8];
    const float* lnb  = (const float*)d_in[9];
    float* out = (float*)d_out;

    const int smemA = 8192 + 64*145*4;            // 45312
    const int smemG = 3*STG*2;                    // 92160
    const int smem4 = (16*SM4_STRIDE + 32) * 4;
    cudaFuncSetAttribute(k_prepA, cudaFuncAttributeMaxDynamicSharedMemorySize, smemA);
    cudaFuncSetAttribute(k_gemm,  cudaFuncAttributeMaxDynamicSharedMemorySize, smemG);
    cudaFuncSetAttribute(k_final, cudaFuncAttributeMaxDynamicSharedMemorySize, smem4);

    k_prepB<<<1152, 256>>>(Wt);
    k_prepA<<<512, 256, smemA>>>(caps);
    k_gemm<<<148, 512, smemG>>>(bt);
    k_route<<<NPTS/4, 256>>>(Wv, bv);
    k_gate<<<NPTS/32, 256>>>(Ws);
    k_bnstats<<<1, 256>>>();
    k_final<<<256, 256, smem4>>>(bng, bnb, lng, lnb, out);
}

// round 17
// speedup vs baseline: 2.3464x; 1.0212x over previous
#include <cuda_runtime.h>
#include <cuda_fp16.h>
#include <math.h>
#include <stdint.h>
#include <string.h>

// Problem constants
#define BATCH 32
#define CIN   8
#define COUT  8
#define KP    4
#define DIN   16
#define DOUT  16
#define SS_   32
#define EPSV  1e-5f

#define NPTS  (BATCH*SS_*SS_)      // 32768 spatial points (b,y,x)
#define NOC   (CIN*COUT*DOUT)      // 1024 conv output channels
#define KDIM  144                  // GEMM K (fp32)
#define KE2   288                  // [hi(144) | lo(144)] fp16 layout
#define OD    (COUT*DOUT)          // 128 (o,d) pairs per point

typedef unsigned long long u64;

// ---------------- packed f32x2 helpers ------------------------------------
__device__ __forceinline__ u64 pack2(float lo, float hi) {
    u64 d; asm("mov.b64 %0,{%1,%2};" : "=l"(d) : "f"(lo), "f"(hi)); return d;
}
__device__ __forceinline__ u64 ffma2(u64 a, u64 b, u64 c) {
    u64 d; asm("fma.rn.f32x2 %0,%1,%2,%3;" : "=l"(d) : "l"(a), "l"(b), "l"(c)); return d;
}
__device__ __forceinline__ u64 fadd2(u64 a, u64 b) {
    u64 d; asm("add.rn.f32x2 %0,%1,%2;" : "=l"(d) : "l"(a), "l"(b)); return d;
}
__device__ __forceinline__ void unpack2(u64 d, float& lo, float& hi) {
    asm("mov.b64 {%0,%1},%2;" : "=f"(lo), "=f"(hi) : "l"(d));
}

__device__ __forceinline__ uint32_t smem_u32(const void* p) {
    uint32_t a;
    asm("{ .reg .u64 t; cvta.to.shared.u64 t, %1; cvt.u32.u64 %0, t; }" : "=r"(a) : "l"(p));
    return a;
}
#define CP_ASYNC16(dst, src) asm volatile("cp.async.cg.shared.global [%0], [%1], 16;" :: "r"(dst), "l"(src))
#define CP_COMMIT()          asm volatile("cp.async.commit_group;" ::: "memory")

#define MMAF16(d, a0, a1, a2, a3, b0, b1) \
    asm volatile("mma.sync.aligned.m16n8k16.row.col.f32.f16.f16.f32 " \
        "{%0,%1,%2,%3},{%4,%5,%6,%7},{%8,%9},{%0,%1,%2,%3};" \
        : "+f"((d)[0]), "+f"((d)[1]), "+f"((d)[2]), "+f"((d)[3]) \
        : "r"(a0), "r"(a1), "r"(a2), "r"(a3), "r"(b0), "r"(b1))

#define LDSM4(r0, r1, r2, r3, addr) \
    asm volatile("ldmatrix.sync.aligned.m8n8.x4.shared.b16 {%0,%1,%2,%3}, [%4];" \
        : "=r"(r0), "=r"(r1), "=r"(r2), "=r"(r3) : "r"(addr))

// fp16 pack/unpack helpers
__device__ __forceinline__ void unp8(uint4 u, float* o) {
    float2 f;
    f = __half22float2(*(__half2*)&u.x); o[0]=f.x; o[1]=f.y;
    f = __half22float2(*(__half2*)&u.y); o[2]=f.x; o[3]=f.y;
    f = __half22float2(*(__half2*)&u.z); o[4]=f.x; o[5]=f.y;
    f = __half22float2(*(__half2*)&u.w); o[6]=f.x; o[7]=f.y;
}
__device__ __forceinline__ uint4 pk8(const float* a) {
    uint4 u; __half2 h;
    h = __floats2half2_rn(a[0], a[1]); u.x = *(uint32_t*)&h;
    h = __floats2half2_rn(a[2], a[3]); u.y = *(uint32_t*)&h;
    h = __floats2half2_rn(a[4], a[5]); u.z = *(uint32_t*)&h;
    h = __floats2half2_rn(a[6], a[7]); u.w = *(uint32_t*)&h;
    return u;
}

// ---------------- scratch (device globals) --------------------------------
__device__ __align__(128) __half g_Ab[NPTS*KE2];    // im2col A [p][hi144|lo144]
__device__ __align__(128) __half g_Bb[NOC*KE2];     // weights  [oc][hi144|lo144]
__device__ __align__(128) __half g_votes[NPTS*NOC]; // conv output, fp16 [pt][oc]
__device__ __align__(128) float  g_sumAtt[NPTS*OD]; // fp32 (feeds output directly)
__device__ __align__(128) __half g_pmax[NPTS*OD];
__device__ __align__(128) __half g_pmean[NPTS*OD];
__device__ __align__(128) __half g_gate[NPTS*OD];
__device__ float g_psumArr[1024*8];
__device__ float g_pssArr[1024*8];
__device__ float g_bnMu[8];
__device__ float g_bnRstd[8];

// ---------------- kernel: prep B (fp16 split Wt -> [oc][288]) -------------
__global__ void k_prepB(const float* __restrict__ Wt) {
    int idx = blockIdx.x * 256 + threadIdx.x;   // 1152 blocks exact (294912)
    int oc = idx / KE2, e = idx % KE2;
    int t = e / KDIM, k = e - t*KDIM;
    float w = Wt[oc*KDIM + k];
    float hi = __half2float(__float2half_rn(w));
    float v = t ? (w - hi) : hi;
    g_Bb[idx] = __float2half_rn(v);
}

// ---------------- kernel: prep A (im2col + fp16 split -> [p][288]) --------
__global__ __launch_bounds__(256) void k_prepA(const float* __restrict__ caps) {
    extern __shared__ char dyn_sm[];
    float* raw = (float*)dyn_sm;                   // 2048 f
    uint32_t* outp = (uint32_t*)(dyn_sm + 8192);   // [64][145] u32
    int tid = threadIdx.x;
    int m064 = blockIdx.x * 64;
    int b = m064 >> 10;
    int y0 = (m064 & 1023) >> 5;
    for (int i = tid; i < 2048; i += 256) {
        int din = i >> 7, rem = i & 127, yy = y0 - 1 + (rem >> 5), x = rem & 31;
        raw[i] = ((unsigned)yy < 32u) ? caps[b*16384 + din*1024 + yy*32 + x] : 0.f;
    }
    __syncthreads();
    int p = tid & 63, part = tid >> 6;
    int y_local = p >> 5, x = p & 31;
    bool isLo = part >= 2;
    int j0 = (part & 1) * 36;
    for (int j = j0; j < j0 + 36; j++) {
        float v[2];
#pragma unroll
        for (int q = 0; q < 2; q++) {
            int k = 2*j + q;
            int din = k / 9, r = k - din*9;
            int ry = r / 3;
            int xx = x + (r - ry*3) - 1;
            v[q] = ((unsigned)xx < 32u) ? raw[din*128 + (y_local + ry)*32 + xx] : 0.f;
        }
        uint32_t u;
        if (!isLo) {
            __half2 h2 = __floats2half2_rn(v[0], v[1]);
            memcpy(&u, &h2, 4);
            outp[p*145 + j] = u;
        } else {
            float h0 = __half2float(__float2half_rn(v[0]));
            float h1 = __half2float(__float2half_rn(v[1]));
            __half2 l2 = __floats2half2_rn(v[0]-h0, v[1]-h1);
            memcpy(&u, &l2, 4);
            outp[p*145 + 72 + j] = u;
        }
    }
    __syncthreads();
    uint32_t* gdst = (uint32_t*)((char*)g_Ab + (size_t)m064 * (KE2*2));
    for (int i = tid; i < 64*144; i += 256)
        gdst[i] = outp[(i/144)*145 + (i%144)];
}

// ---------------- kernel: persistent fp16 GEMM votes = A x B^T + bias -----
// 148 blocks, continuous 3-stage cp.async pipeline, ldmatrix fragment loads.
#define STG 15360
#define NTILES 1024    // (8 n) x (128 m)
__device__ __forceinline__ void gloadG(uint32_t dbase, int g, int bid, int tid) {
    int tt = g / 9, c = g - tt*9;
    int t  = bid + 148*tt;
    const char* Asrc = (const char*)g_Ab + (size_t)((t >> 3)*256) * 576;
    const char* Bsrc = (const char*)g_Bb + (size_t)((t & 7)*128) * 576;
#pragma unroll
    for (int i = 0; i < 2; i++) {
        int q = i*512 + tid;
        int row = q >> 2, part = q & 3;
        uint32_t dst = dbase + row*80 + ((part < 2) ? 0 : 32) + (part & 1)*16;
        CP_ASYNC16(dst, Asrc + (size_t)row*576 + ((part < 2) ? 0 : 288) + c*32 + (part & 1)*16);
    }
    if ((tid & 3) < 2) {               // B: hi only
        int row = tid >> 2, part = tid & 1;
        uint32_t dst = dbase + 20480 + row*80 + part*16;
        CP_ASYNC16(dst, Bsrc + (size_t)row*576 + c*32 + part*16);
    }
}

__global__ __launch_bounds__(512, 1) void k_gemm(const float* __restrict__ bt) {
    extern __shared__ char dyn_sm[];
    __half* gsm = (__half*)dyn_sm;
    const int tid = threadIdx.x;
    const int lane = tid & 31;
    const int wid = tid >> 5;
    const int warpM = wid & 3;
    const int warpN = wid >> 2;
    const int bid = blockIdx.x;
    const uint32_t sb = smem_u32(gsm);

    const int nt = (NTILES - bid + 147) / 148;
    const int G  = nt * 9;

    gloadG(sb,          0, bid, tid); CP_COMMIT();
    gloadG(sb + STG*2,  1, bid, tid); CP_COMMIT();

    float acc[4][4][4];
#pragma unroll
    for (int a = 0; a < 4; a++)
#pragma unroll
        for (int b = 0; b < 4; b++)
#pragma unroll
            for (int c = 0; c < 4; c++) acc[a][b][c] = 0.f;

    const int qr = lane >> 2;
    const int qc = lane & 3;
    // ldmatrix per-lane byte offsets within a stage
    const uint32_t aoff = (uint32_t)(((lane & 7) + ((lane >> 3) & 1)*8)*80 + (lane >> 4)*16);
    const uint32_t boff = (uint32_t)(20480 + ((lane & 7) + ((lane >> 4) & 1)*8)*80 + ((lane >> 3) & 1)*16);
    const uint32_t abase = sb + (uint32_t)(warpM*64*80) + aoff;
    const uint32_t bbase = sb + (uint32_t)(warpN*32*80) + boff;

    for (int g = 0; g < G; g++) {
        if (g == G-1) asm volatile("cp.async.wait_group 0;" ::: "memory");
        else          asm volatile("cp.async.wait_group 1;" ::: "memory");
        __syncthreads();
        if (g + 2 < G) {
            gloadG(sb + ((g+2)%3)*STG*2, g+2, bid, tid);
            CP_COMMIT();
        }
        const uint32_t soff = (uint32_t)((g % 3) * (STG*2));

        uint32_t ah[4][4], bh[4][2];
#pragma unroll
        for (int mf = 0; mf < 4; mf++)
            LDSM4(ah[mf][0], ah[mf][1], ah[mf][2], ah[mf][3], abase + soff + mf*1280);
#pragma unroll
        for (int pr = 0; pr < 2; pr++)
            LDSM4(bh[2*pr][0], bh[2*pr][1], bh[2*pr+1][0], bh[2*pr+1][1],
                  bbase + soff + pr*1280);
#pragma unroll
        for (int mf = 0; mf < 4; mf++)
#pragma unroll
            for (int nf = 0; nf < 4; nf++)
                MMAF16(acc[mf][nf], ah[mf][0], ah[mf][1], ah[mf][2], ah[mf][3],
                       bh[nf][0], bh[nf][1]);
#pragma unroll
        for (int mf = 0; mf < 4; mf++) {
            uint32_t al0, al1, al2, al3;
            LDSM4(al0, al1, al2, al3, abase + soff + mf*1280 + 32);   // lo at +16 halves
#pragma unroll
            for (int nf = 0; nf < 4; nf++)
                MMAF16(acc[mf][nf], al0, al1, al2, al3, bh[nf][0], bh[nf][1]);
        }

        if ((g % 9) == 8) {
            int t  = bid + 148*(g/9);
            int m0 = (t >> 3)*256;
            int n0 = (t & 7)*128;
#pragma unroll
            for (int mf = 0; mf < 4; mf++) {
                int row0 = m0 + warpM*64 + mf*16 + qr;
#pragma unroll
                for (int nf = 0; nf < 4; nf++) {
                    int cl = warpN*32 + nf*8 + qc*2;
                    float2 bb = *(const float2*)(bt + n0 + cl);
                    __half2 h0 = __floats2half2_rn(acc[mf][nf][0] + bb.x, acc[mf][nf][1] + bb.y);
                    __half2 h1 = __floats2half2_rn(acc[mf][nf][2] + bb.x, acc[mf][nf][3] + bb.y);
                    *(__half2*)(g_votes + (size_t)row0*1024 + n0 + cl) = h0;
                    *(__half2*)(g_votes + (size_t)(row0+8)*1024 + n0 + cl) = h1;
                    acc[mf][nf][0] = 0.f; acc[mf][nf][1] = 0.f;
                    acc[mf][nf][2] = 0.f; acc[mf][nf][3] = 0.f;
                }
            }
        }
    }
}

// ---------------- kernel 2: values + pooling + agreement routing ----------
__global__ __launch_bounds__(256) void k_route(const float* __restrict__ Wv,
                                               const float* __restrict__ bv) {
    __shared__ __align__(16) float wv_s[2048];
    __shared__ float bv_s[256];
    int tid = threadIdx.x;
    for (int i = tid; i < 2048; i += 256) wv_s[i] = Wv[i];
    if (tid < 256) bv_s[tid] = bv[tid];
    __syncthreads();

    int pt  = blockIdx.x * 4 + (tid >> 6);
    int l64 = tid & 63;
    int o   = l64 >> 3;
    const __half* vp = g_votes + (size_t)pt * 1024 + l64 * 2;

    u64 vt2[8];
#pragma unroll
    for (int c = 0; c < 8; c++) {
        __half2 h = *(const __half2*)(vp + c*128);
        float2 f = __half22float2(h);
        vt2[c] = pack2(f.x, f.y);
    }

    float av[2] = {0.f, 0.f};
    float wsum[2] = {0.f, 0.f};
    float pmax[2] = {-1e30f, -1e30f};
    float ps0 = 0.f, ps1 = 0.f;

    const float4* wv4 = (const float4*)wv_s;
#pragma unroll
    for (int c2 = 0; c2 < 8; c2++) {
        u64 ks = 0ULL, kq = 0ULL;
#pragma unroll
        for (int kp = 0; kp < 4; kp++) {
            int m = kp*8 + c2;
            float4 wa = wv4[(o*32 + m)*2 + 0];
            float4 wb = wv4[(o*32 + m)*2 + 1];
            float bvv = bv_s[o*32 + m];
            u64 v0 = pack2(bvv, bvv), v1 = 0ULL, w;
            w = pack2(wa.x, wa.x); v0 = ffma2(w, vt2[0], v0);
            w = pack2(wa.y, wa.y); v1 = ffma2(w, vt2[1], v1);
            w = pack2(wa.z, wa.z); v0 = ffma2(w, vt2[2], v0);
            w = pack2(wa.w, wa.w); v1 = ffma2(w, vt2[3], v1);
            w = pack2(wb.x, wb.x); v0 = ffma2(w, vt2[4], v0);
            w = pack2(wb.y, wb.y); v1 = ffma2(w, vt2[5], v1);
            w = pack2(wb.z, wb.z); v0 = ffma2(w, vt2[6], v0);
            w = pack2(wb.w, wb.w); v1 = ffma2(w, vt2[7], v1);
            u64 v = fadd2(v0, v1);
            ks = fadd2(ks, v);
            kq = ffma2(v, v, kq);
            float f0, f1;
            unpack2(v, f0, f1);
            pmax[0] = fmaxf(pmax[0], f0);
            pmax[1] = fmaxf(pmax[1], f1);
        }
        float ksf0, ksf1, kqf0, kqf1;
        unpack2(ks, ksf0, ksf1);
        unpack2(kq, kqf0, kqf1);
        ps0 += ksf0; ps1 += ksf1;
        {
            float mu  = ksf0 * 0.25f;
            float var = fmaxf(kqf0 * 0.25f - mu*mu, 1e-30f);
            float rs  = rsqrtf(var);
            av[0] += mu * rs; wsum[0] += rs;
        }
        {
            float mu  = ksf1 * 0.25f;
            float var = fmaxf(kqf1 * 0.25f - mu*mu, 1e-30f);
            float rs  = rsqrtf(var);
            av[1] += mu * rs; wsum[1] += rs;
        }
    }

    size_t off = (size_t)pt*128 + l64*2;
    *(float2*)(g_sumAtt + off) = make_float2(av[0]/wsum[0], av[1]/wsum[1]);
    *(__half2*)(g_pmax  + off) = __floats2half2_rn(pmax[0], pmax[1]);
    *(__half2*)(g_pmean + off) = __floats2half2_rn(ps0 * (1.f/32.f), ps1 * (1.f/32.f));
}

// ---------------- kernel 3: 3D gate conv (3x3x3, pad1) + BN partials -----
__global__ __launch_bounds__(256) void k_gate(const float* __restrict__ Ws) {
    __shared__ float ws_s[54];
    __shared__ float bsum[8], bss[8];
    int tid = threadIdx.x;
    if (tid < 54) ws_s[tid] = Ws[tid];
    if (tid < 8) { bsum[tid] = 0.f; bss[tid] = 0.f; }
    __syncthreads();

    int pt = blockIdx.x * 32 + (tid >> 3);
    int o  = tid & 7;
    int b  = pt >> 10, yx = pt & 1023;
    int y  = yx >> 5,  x  = yx & 31;

    float acc[16];
#pragma unroll
    for (int d = 0; d < 16; d++) acc[d] = 0.f;

    for (int dy = -1; dy <= 1; dy++) {
        int yy = y + dy;
        if ((unsigned)yy >= 32u) continue;
        for (int dx = -1; dx <= 1; dx++) {
            int xx = x + dx;
            if ((unsigned)xx >= 32u) continue;
            int base = ((b << 10) + (yy << 5) + xx)*128 + (o << 4);
            const uint4* pmx = (const uint4*)(g_pmax  + base);
            const uint4* pmn = (const uint4*)(g_pmean + base);
            float rmx[16], rmn[16];
            unp8(pmx[0], rmx); unp8(pmx[1], rmx + 8);
            unp8(pmn[0], rmn); unp8(pmn[1], rmn + 8);
            int wo = (dy+1)*3 + (dx+1);
#pragma unroll
            for (int kz = 0; kz < 3; kz++) {
                float wm = ws_s[kz*9 + wo];
                float wn = ws_s[27 + kz*9 + wo];
#pragma unroll
                for (int d = 0; d < 16; d++) {
                    int s = d + kz - 1;
                    if (s >= 0 && s < 16) acc[d] += wm*rmx[s] + wn*rmn[s];
                }
            }
        }
    }
    __half* gp = g_gate + (size_t)pt*128 + (o << 4);
    *(uint4*)gp       = pk8(acc);
    *(uint4*)(gp + 8) = pk8(acc + 8);

    float s1 = 0.f, s2 = 0.f;
#pragma unroll
    for (int d = 0; d < 16; d++) { s1 += acc[d]; s2 += acc[d]*acc[d]; }
    s1 += __shfl_xor_sync(0xffffffffu, s1, 8);
    s2 += __shfl_xor_sync(0xffffffffu, s2, 8);
    s1 += __shfl_xor_sync(0xffffffffu, s1, 16);
    s2 += __shfl_xor_sync(0xffffffffu, s2, 16);
    if ((tid & 31) < 8) { atomicAdd(&bsum[o], s1); atomicAdd(&bss[o], s2); }
    __syncthreads();
    if (tid < 8) {
        g_psumArr[blockIdx.x*8 + tid] = bsum[tid];
        g_pssArr [blockIdx.x*8 + tid] = bss[tid];
    }
}

// ---------------- kernel 3b: BN stats finalize (1024 partials) ------------
__global__ void k_bnstats() {
    __shared__ float ss1[256], ss2[256];
    int tid = threadIdx.x;
    int o = tid & 7, seg = tid >> 3;
    float a = 0.f, c = 0.f;
    for (int i = seg*32; i < seg*32 + 32; i++) {
        a += g_psumArr[i*8 + o];
        c += g_pssArr [i*8 + o];
    }
    ss1[tid] = a; ss2[tid] = c;
    __syncthreads();
    if (tid < 8) {
        float A = 0.f, C = 0.f;
        for (int s = 0; s < 32; s++) { A += ss1[s*8 + tid]; C += ss2[s*8 + tid]; }
        const float inv = 1.f / 524288.f;
        float mu = A * inv;
        float var = C * inv - mu*mu;
        g_bnMu[tid]   = mu;
        g_bnRstd[tid] = rsqrtf(var + EPSV);
    }
}

// ---------------- kernel 4: gate apply + LayerNorm + transpose out -------
#define SM4_STRIDE 1025
__global__ __launch_bounds__(256) void k_final(const float* __restrict__ bn_gamma,
                                               const float* __restrict__ bn_beta,
                                               const float* __restrict__ ln_gamma,
                                               const float* __restrict__ ln_beta,
                                               float* __restrict__ out) {
    extern __shared__ char dyn_sm[];
    float* sm4 = (float*)dyn_sm;
    const int RED = 16*SM4_STRIDE;
    int tid = threadIdx.x;
    int b = blockIdx.x & 31;
    int o = blockIdx.x >> 5;
    float mu = g_bnMu[o], rstd = g_bnRstd[o];
    float gam = bn_gamma[0], bet = bn_beta[0];

    int d   = tid & 15;
    int yxb = tid >> 4;
    const __half* gp = g_gate   + (size_t)(b << 10)*128 + (o << 4) + d;
    const float*  sp = g_sumAtt + (size_t)(b << 10)*128 + (o << 4) + d;
    float s = 0.f, ss = 0.f;
    for (int i = 0; i < 64; i++) {
        int yx = yxb + i*16;
        float gg = __half2float(gp[yx*128]);
        float sa = sp[yx*128];
        float z  = (gg - mu) * rstd * gam + bet;
        float sc = 1.f / (1.f + expf(-z));
        float cn = (1.f + sc) * sa;
        sm4[d*SM4_STRIDE + yx] = cn;
        s += cn; ss += cn*cn;
    }
#pragma unroll
    for (int off = 16; off >= 1; off >>= 1) {
        s  += __shfl_xor_sync(0xffffffffu, s,  off);
        ss += __shfl_xor_sync(0xffffffffu, ss, off);
    }
    int wid = tid >> 5;
    if ((tid & 31) == 0) { sm4[RED + wid] = s; sm4[RED + 8 + wid] = ss; }
    __syncthreads();
    if (tid == 0) {
        float S = 0.f, Q = 0.f;
        for (int w = 0; w < 8; w++) { S += sm4[RED + w]; Q += sm4[RED + 8 + w]; }
        const float inv = 1.f / 16384.f;
        float m = S * inv;
        float var = Q * inv - m*m;
        sm4[RED + 16] = m;
        sm4[RED + 17] = rsqrtf(var + EPSV);
    }
    __syncthreads();
    float m = sm4[RED + 16], r = sm4[RED + 17];
    float* ob = out + ((o*32 + b) << 14);
    for (int i = 0; i < 64; i++) {
        int idx = i*256 + tid;
        float v = sm4[(idx >> 10)*SM4_STRIDE + (idx & 1023)];
        ob[idx] = (v - m) * r * ln_gamma[idx] + ln_beta[idx];
    }
}

// ---------------- launch ------------------------------------------------
extern "C" void kernel_launch(void* const* d_in, const int* in_sizes, int n_in,
                              void* d_out, int out_size) {
    const float* caps = (const float*)d_in[0];
    const float* Wt   = (const float*)d_in[1];
    const float* bt   = (const float*)d_in[2];
    const float* Wv   = (const float*)d_in[3];
    const float* bv   = (const float*)d_in[4];
    const float* Ws   = (const float*)d_in[5];
    const float* bng  = (const float*)d_in[6];
    const float* bnb  = (const float*)d_in[7];
    const float* lng  = (const float*)d_in[8];
    const float* lnb  = (const float*)d_in[9];
    float* out = (float*)d_out;

    const int smemA = 8192 + 64*145*4;            // 45312
    const int smemG = 3*STG*2;                    // 92160
    const int smem4 = (16*SM4_STRIDE + 32) * 4;
    cudaFuncSetAttribute(k_prepA, cudaFuncAttributeMaxDynamicSharedMemorySize, smemA);
    cudaFuncSetAttribute(k_gemm,  cudaFuncAttributeMaxDynamicSharedMemorySize, smemG);
    cudaFuncSetAttribute(k_final, cudaFuncAttributeMaxDynamicSharedMemorySize, smem4);

    k_prepB<<<1152, 256>>>(Wt);
    k_prepA<<<512, 256, smemA>>>(caps);
    k_gemm<<<148, 512, smemG>>>(bt);
    k_route<<<NPTS/4, 256>>>(Wv, bv);
    k_gate<<<NPTS/32, 256>>>(Ws);
    k_bnstats<<<1, 256>>>();
    k_final<<<256, 256, smem4>>>(bng, bnb, lng, lnb, out);
}